// round 2
// baseline (speedup 1.0000x reference)
#include <cuda_runtime.h>
#include <cstdint>

// ---------------- problem constants ----------------
#define BATCH 128
#define CH    256
#define TT    30
#define HH    16
#define WW    11
#define HW    176
#define NBINS 31
#define RED   16
#define KDIM  4096
#define OUT   256
#define NCLS  10000
#define NB    (NBINS*BATCH)
#define SPLITK 4

// ---------------- scratch ----------------
__device__ float g_p[(size_t)NBINS*BATCH*TT*CH];
__device__ float g_pmax[NBINS*BATCH*CH];
__device__ float g_pooled[(size_t)NBINS*BATCH*KDIM];
__device__ float g_feat[NBINS*BATCH*CH];
__device__ float g_bn[NBINS*BATCH*OUT];
__device__ float g_invrn[NB];
__device__ float g_part[(size_t)SPLITK*NBINS*BATCH*OUT];

// ---------------- f32x2 helpers ----------------
__device__ __forceinline__ uint64_t dup2(float v) {
    uint64_t r;
    asm("mov.b64 %0, {%1, %1};" : "=l"(r) : "r"(__float_as_uint(v)));
    return r;
}
#define FMA2(acc, a, b) asm("fma.rn.f32x2 %0, %1, %2, %0;" : "+l"(acc) : "l"(a), "l"(b))
__device__ __forceinline__ void unpack2(uint64_t v, float& lo, float& hi) {
    unsigned a, b;
    asm("mov.b64 {%0, %1}, %2;" : "=r"(a), "=r"(b) : "l"(v));
    lo = __uint_as_float(a); hi = __uint_as_float(b);
}

// =====================================================================
// K1: horizontal strip pooling (unchanged; DRAM-bound).
// =====================================================================
__global__ __launch_bounds__(512) void k1_hmap(const float* __restrict__ x) {
    int bid = blockIdx.x;
    int cg = bid & 7;
    int t  = (bid >> 3) % TT;
    int b  = bid / (TT * 8);

    __shared__ float xs[32][180];
    __shared__ float rsum[32][16];
    __shared__ float rmax[32][16];

    const float* xb = x + (((size_t)b*CH + cg*32)*TT + t) * HW;
    int tid = threadIdx.x;

    for (int idx = tid; idx < 32*44; idx += 512) {
        int c = idx / 44, e = idx % 44;
        float4 v = *reinterpret_cast<const float4*>(xb + (size_t)c*TT*HW + e*4);
        *reinterpret_cast<float4*>(&xs[c][e*4]) = v;
    }
    __syncthreads();

    {
        int c = tid >> 4, h = tid & 15;
        float s = 0.f, m = -1e30f;
        #pragma unroll
        for (int w = 0; w < WW; ++w) {
            float v = xs[c][h*WW + w];
            s += v; m = fmaxf(m, v);
        }
        rsum[c][h] = s; rmax[c][h] = m;
    }
    __syncthreads();

    for (int oi = tid; oi < NBINS*32; oi += 512) {
        int n = oi >> 5;
        int c = oi & 31;
        int start, len;
        if      (n == 0) { start = 0;          len = 16; }
        else if (n < 3)  { start = (n-1)*8;    len = 8;  }
        else if (n < 7)  { start = (n-3)*4;    len = 4;  }
        else if (n < 15) { start = (n-7)*2;    len = 2;  }
        else             { start = n-15;       len = 1;  }
        float s = 0.f, m = -1e30f;
        for (int h = 0; h < len; ++h) {
            s += rsum[c][start+h];
            m = fmaxf(m, rmax[c][start+h]);
        }
        float val = s / (float)(len*WW) + m;
        g_p[(((size_t)n*BATCH + b)*TT + t)*CH + cg*32 + c] = val;
    }
}

// =====================================================================
// K2: mask logits + softmax + attention pooling + pmax. 512 threads.
// =====================================================================
__global__ __launch_bounds__(512) void k2_mask(const float* __restrict__ Wmask) {
    int nb = blockIdx.x;
    int n = nb >> 7;
    int b = nb & 127;
    __shared__ float ps[TT][CH];
    __shared__ float wms[CH][RED];
    __shared__ float lg[TT][RED];

    int tid = threadIdx.x;
    const float* pg = g_p + ((size_t)n*BATCH + b)*TT*CH;
    for (int i = tid; i < TT*CH/4; i += 512) {
        float4 v = *reinterpret_cast<const float4*>(pg + i*4);
        *reinterpret_cast<float4*>(&ps[0][0] + i*4) = v;
    }
    const float* wg = Wmask + (size_t)n*CH*RED;
    for (int i = tid; i < CH*RED/4; i += 512) {
        float4 v = *reinterpret_cast<const float4*>(wg + i*4);
        *reinterpret_cast<float4*>(&wms[0][0] + i*4) = v;
    }
    __syncthreads();

    // logits [30,16]: thread = (t, r)
    if (tid < TT*RED) {
        int t = tid >> 4, r = tid & 15;
        float acc = 0.f;
        #pragma unroll 8
        for (int c = 0; c < CH; ++c) acc += ps[t][c] * wms[c][r];
        lg[t][r] = acc;
    }
    __syncthreads();

    // softmax over T per column r
    if (tid < RED) {
        int r = tid;
        float m = -1e30f;
        for (int t = 0; t < TT; ++t) m = fmaxf(m, lg[t][r]);
        float s = 0.f;
        for (int t = 0; t < TT; ++t) { float e = expf(lg[t][r] - m); lg[t][r] = e; s += e; }
        float inv = 1.f / s;
        for (int t = 0; t < TT; ++t) lg[t][r] *= inv;
    }
    __syncthreads();

    // pooled[c][r] + pmax[c]; thread = (c, half of r)
    {
        int c = tid & 255;
        int rh = tid >> 8;           // 0 or 1, handles 8 r each
        float acc[8];
        #pragma unroll
        for (int r = 0; r < 8; ++r) acc[r] = 0.f;
        float pm = -1e30f;
        for (int t = 0; t < TT; ++t) {
            float pv = ps[t][c];
            pm = fmaxf(pm, pv);
            float4 m0 = *reinterpret_cast<const float4*>(&lg[t][rh*8]);
            float4 m1 = *reinterpret_cast<const float4*>(&lg[t][rh*8+4]);
            acc[0] += pv*m0.x; acc[1] += pv*m0.y; acc[2] += pv*m0.z; acc[3] += pv*m0.w;
            acc[4] += pv*m1.x; acc[5] += pv*m1.y; acc[6] += pv*m1.z; acc[7] += pv*m1.w;
        }
        float* pd = g_pooled + ((size_t)n*BATCH + b)*KDIM + c*RED + rh*8;
        *reinterpret_cast<float4*>(pd)     = make_float4(acc[0],acc[1],acc[2],acc[3]);
        *reinterpret_cast<float4*>(pd + 4) = make_float4(acc[4],acc[5],acc[6],acc[7]);
        if (rh == 0) g_pmax[((size_t)n*BATCH + b)*CH + c] = pm;
    }
}

// =====================================================================
// K3: split-K partials of pooled @ Wout.  128x128x8 f32x2 GEMM.
// grid (1 Ntile... actually N=256 -> 2 Ntiles, NBINS, SPLITK)
// =====================================================================
__global__ __launch_bounds__(256, 2) void k3_wout(const float* __restrict__ Wout) {
    int n  = blockIdx.y;
    int n0 = blockIdx.x * 128;
    int kq = blockIdx.z;
    const int KCH = KDIM / SPLITK;          // 1024
    int kbase = kq * KCH;
    const float* A = g_pooled + (size_t)n*BATCH*KDIM;
    const float* B = Wout + (size_t)n*KDIM*OUT;

    __shared__ float As[2][8][128];
    __shared__ float Bs[2][8][128];

    int tid = threadIdx.x;
    int arow = tid >> 1, akc = (tid & 1) * 4;
    int brow = tid >> 5, bnc = (tid & 31) * 4;
    int m0 = (tid >> 4) * 8, nn0 = (tid & 15) * 8;

    uint64_t acc[8][4];
    #pragma unroll
    for (int i = 0; i < 8; ++i)
        #pragma unroll
        for (int j = 0; j < 4; ++j) acc[i][j] = 0ULL;

    const int NT = KCH / 8;                 // 128
    float4 rA, rB;
    rA = *reinterpret_cast<const float4*>(A + (size_t)arow*KDIM + kbase + akc);
    rB = *reinterpret_cast<const float4*>(B + (size_t)(kbase + brow)*OUT + n0 + bnc);
    As[0][akc+0][arow] = rA.x; As[0][akc+1][arow] = rA.y;
    As[0][akc+2][arow] = rA.z; As[0][akc+3][arow] = rA.w;
    *reinterpret_cast<float4*>(&Bs[0][brow][bnc]) = rB;
    __syncthreads();

    for (int t = 0; t < NT; ++t) {
        int cur = t & 1;
        if (t + 1 < NT) {
            int k0 = kbase + (t+1)*8;
            rA = *reinterpret_cast<const float4*>(A + (size_t)arow*KDIM + k0 + akc);
            rB = *reinterpret_cast<const float4*>(B + (size_t)(k0 + brow)*OUT + n0 + bnc);
        }
        #pragma unroll
        for (int kk = 0; kk < 8; ++kk) {
            float4 a0 = *reinterpret_cast<const float4*>(&As[cur][kk][m0]);
            float4 a1 = *reinterpret_cast<const float4*>(&As[cur][kk][m0+4]);
            const uint64_t* bp = reinterpret_cast<const uint64_t*>(&Bs[cur][kk][nn0]);
            uint64_t b0 = bp[0], b1 = bp[1], b2 = bp[2], b3 = bp[3];
            float av[8] = {a0.x,a0.y,a0.z,a0.w,a1.x,a1.y,a1.z,a1.w};
            #pragma unroll
            for (int i = 0; i < 8; ++i) {
                uint64_t ad = dup2(av[i]);
                FMA2(acc[i][0], ad, b0); FMA2(acc[i][1], ad, b1);
                FMA2(acc[i][2], ad, b2); FMA2(acc[i][3], ad, b3);
            }
        }
        if (t + 1 < NT) {
            int nxt = 1 - cur;
            As[nxt][akc+0][arow] = rA.x; As[nxt][akc+1][arow] = rA.y;
            As[nxt][akc+2][arow] = rA.z; As[nxt][akc+3][arow] = rA.w;
            *reinterpret_cast<float4*>(&Bs[nxt][brow][bnc]) = rB;
        }
        __syncthreads();
    }

    float* pp = g_part + (((size_t)kq*NBINS + n)*BATCH)*OUT;
    #pragma unroll
    for (int i = 0; i < 8; ++i) {
        int m = m0 + i;
        float v[8];
        #pragma unroll
        for (int j = 0; j < 4; ++j) unpack2(acc[i][j], v[2*j], v[2*j+1]);
        *reinterpret_cast<float4*>(pp + (size_t)m*OUT + n0 + nn0)     = make_float4(v[0],v[1],v[2],v[3]);
        *reinterpret_cast<float4*>(pp + (size_t)m*OUT + n0 + nn0 + 4) = make_float4(v[4],v[5],v[6],v[7]);
    }
}

// K3 epilogue: sum partials, leaky, + pmax -> feat
__global__ __launch_bounds__(256) void k3e_epi() {
    int n = blockIdx.x;
    int c = threadIdx.x;
    const size_t STRIDE = (size_t)NBINS*BATCH*OUT;
    for (int m = 0; m < BATCH; ++m) {
        size_t off = (((size_t)n*BATCH + m))*OUT + c;
        float s = g_part[off] + g_part[STRIDE + off] + g_part[2*STRIDE + off] + g_part[3*STRIDE + off];
        s = (s >= 0.f) ? s : 0.01f*s;
        g_feat[off] = s + g_pmax[off];
    }
}

// =====================================================================
// K4: outputs = feat @ FForward -> out1 [B, n, O]. 128x128x8 f32x2.
// =====================================================================
__global__ __launch_bounds__(256, 2) void k4_ff(const float* __restrict__ FF, float* __restrict__ out1) {
    int n  = blockIdx.y;
    int n0 = blockIdx.x * 128;
    const float* A = g_feat + (size_t)n*BATCH*CH;
    const float* B = FF + (size_t)n*CH*OUT;

    __shared__ float As[2][8][128];
    __shared__ float Bs[2][8][128];

    int tid = threadIdx.x;
    int arow = tid >> 1, akc = (tid & 1) * 4;
    int brow = tid >> 5, bnc = (tid & 31) * 4;
    int m0 = (tid >> 4) * 8, nn0 = (tid & 15) * 8;

    uint64_t acc[8][4];
    #pragma unroll
    for (int i = 0; i < 8; ++i)
        #pragma unroll
        for (int j = 0; j < 4; ++j) acc[i][j] = 0ULL;

    const int NT = CH / 8;  // 32
    float4 rA, rB;
    rA = *reinterpret_cast<const float4*>(A + (size_t)arow*CH + akc);
    rB = *reinterpret_cast<const float4*>(B + (size_t)brow*OUT + n0 + bnc);
    As[0][akc+0][arow] = rA.x; As[0][akc+1][arow] = rA.y;
    As[0][akc+2][arow] = rA.z; As[0][akc+3][arow] = rA.w;
    *reinterpret_cast<float4*>(&Bs[0][brow][bnc]) = rB;
    __syncthreads();

    for (int t = 0; t < NT; ++t) {
        int cur = t & 1;
        if (t + 1 < NT) {
            int k0 = (t+1)*8;
            rA = *reinterpret_cast<const float4*>(A + (size_t)arow*CH + k0 + akc);
            rB = *reinterpret_cast<const float4*>(B + (size_t)(k0 + brow)*OUT + n0 + bnc);
        }
        #pragma unroll
        for (int kk = 0; kk < 8; ++kk) {
            float4 a0 = *reinterpret_cast<const float4*>(&As[cur][kk][m0]);
            float4 a1 = *reinterpret_cast<const float4*>(&As[cur][kk][m0+4]);
            const uint64_t* bp = reinterpret_cast<const uint64_t*>(&Bs[cur][kk][nn0]);
            uint64_t b0 = bp[0], b1 = bp[1], b2 = bp[2], b3 = bp[3];
            float av[8] = {a0.x,a0.y,a0.z,a0.w,a1.x,a1.y,a1.z,a1.w};
            #pragma unroll
            for (int i = 0; i < 8; ++i) {
                uint64_t ad = dup2(av[i]);
                FMA2(acc[i][0], ad, b0); FMA2(acc[i][1], ad, b1);
                FMA2(acc[i][2], ad, b2); FMA2(acc[i][3], ad, b3);
            }
        }
        if (t + 1 < NT) {
            int nxt = 1 - cur;
            As[nxt][akc+0][arow] = rA.x; As[nxt][akc+1][arow] = rA.y;
            As[nxt][akc+2][arow] = rA.z; As[nxt][akc+3][arow] = rA.w;
            *reinterpret_cast<float4*>(&Bs[nxt][brow][bnc]) = rB;
        }
        __syncthreads();
    }

    #pragma unroll
    for (int i = 0; i < 8; ++i) {
        int m = m0 + i;
        float v[8];
        #pragma unroll
        for (int j = 0; j < 4; ++j) unpack2(acc[i][j], v[2*j], v[2*j+1]);
        float* op = out1 + (size_t)m*(NBINS*OUT) + n*OUT + n0 + nn0;
        *reinterpret_cast<float4*>(op)     = make_float4(v[0],v[1],v[2],v[3]);
        *reinterpret_cast<float4*>(op + 4) = make_float4(v[4],v[5],v[6],v[7]);
    }
}

// =====================================================================
// K5: per-bin BatchNorm (two-pass).
// =====================================================================
__global__ __launch_bounds__(256) void k5_bn(const float* __restrict__ out1,
                                             const float* __restrict__ gamma,
                                             const float* __restrict__ beta) {
    int n = blockIdx.x, o = threadIdx.x;
    const float* base = out1 + n*OUT + o;
    const int STR = NBINS*OUT;
    float s = 0.f;
    #pragma unroll 4
    for (int b = 0; b < BATCH; ++b) s += base[(size_t)b*STR];
    float mean = s * (1.f/BATCH);
    float v = 0.f;
    #pragma unroll 4
    for (int b = 0; b < BATCH; ++b) { float d = base[(size_t)b*STR] - mean; v += d*d; }
    v *= (1.f/BATCH);
    float istd = rsqrtf(v + 1e-5f);
    float g = gamma[n*OUT + o], be = beta[n*OUT + o];
    float* bnp = g_bn + (size_t)n*BATCH*OUT + o;
    #pragma unroll 4
    for (int b = 0; b < BATCH; ++b)
        bnp[(size_t)b*OUT] = g * (base[(size_t)b*STR] - mean) * istd + be;
}

// K5b: inverse row L2 norms of bn
__global__ __launch_bounds__(64) void k5b_rn() {
    int nb = blockIdx.x;
    int tid = threadIdx.x;
    const float* r = g_bn + (size_t)nb*OUT;
    float s = 0.f;
    for (int i = tid; i < OUT; i += 64) { float v = r[i]; s += v*v; }
    #pragma unroll
    for (int o = 16; o > 0; o >>= 1) s += __shfl_xor_sync(0xffffffffu, s, o);
    __shared__ float ws[2];
    if ((tid & 31) == 0) ws[tid >> 5] = s;
    __syncthreads();
    if (tid == 0) g_invrn[nb] = 1.f / fmaxf(sqrtf(ws[0] + ws[1]), 1e-12f);
}

// =====================================================================
// K6: logits = (bn @ fc1d) * invrow * invcol. 128x128x8 f32x2 GEMM,
// column sumsq fused into the global-load path.
// =====================================================================
__global__ __launch_bounds__(256, 2) void k6_logits(const float* __restrict__ fc,
                                                    float* __restrict__ out2) {
    int n  = blockIdx.y;
    int n0 = blockIdx.x * 128;
    const float* A = g_bn + (size_t)n*BATCH*OUT;
    const float* B = fc + (size_t)n*OUT*NCLS;

    __shared__ float As[2][8][128];
    __shared__ float Bs[2][8][128];
    __shared__ float sqs[8][128];

    int tid = threadIdx.x;
    int arow = tid >> 1, akc = (tid & 1) * 4;
    int brow = tid >> 5, bnc = (tid & 31) * 4;
    int m0 = (tid >> 4) * 8, nn0 = (tid & 15) * 8;
    bool bvalid = (n0 + bnc) < NCLS;   // float4 is fully in or out (4 | 10000)

    uint64_t acc[8][4];
    #pragma unroll
    for (int i = 0; i < 8; ++i)
        #pragma unroll
        for (int j = 0; j < 4; ++j) acc[i][j] = 0ULL;
    float4 bsq = make_float4(0.f,0.f,0.f,0.f);

    const int NT = OUT / 8;  // 32
    float4 rA, rB;
    rA = *reinterpret_cast<const float4*>(A + (size_t)arow*OUT + akc);
    rB = bvalid ? *reinterpret_cast<const float4*>(B + (size_t)brow*NCLS + n0 + bnc)
                : make_float4(0.f,0.f,0.f,0.f);
    bsq.x += rB.x*rB.x; bsq.y += rB.y*rB.y; bsq.z += rB.z*rB.z; bsq.w += rB.w*rB.w;
    As[0][akc+0][arow] = rA.x; As[0][akc+1][arow] = rA.y;
    As[0][akc+2][arow] = rA.z; As[0][akc+3][arow] = rA.w;
    *reinterpret_cast<float4*>(&Bs[0][brow][bnc]) = rB;
    __syncthreads();

    for (int t = 0; t < NT; ++t) {
        int cur = t & 1;
        if (t + 1 < NT) {
            int k0 = (t+1)*8;
            rA = *reinterpret_cast<const float4*>(A + (size_t)arow*OUT + k0 + akc);
            rB = bvalid ? *reinterpret_cast<const float4*>(B + (size_t)(k0 + brow)*NCLS + n0 + bnc)
                        : make_float4(0.f,0.f,0.f,0.f);
            bsq.x += rB.x*rB.x; bsq.y += rB.y*rB.y; bsq.z += rB.z*rB.z; bsq.w += rB.w*rB.w;
        }
        #pragma unroll
        for (int kk = 0; kk < 8; ++kk) {
            float4 a0 = *reinterpret_cast<const float4*>(&As[cur][kk][m0]);
            float4 a1 = *reinterpret_cast<const float4*>(&As[cur][kk][m0+4]);
            const uint64_t* bp = reinterpret_cast<const uint64_t*>(&Bs[cur][kk][nn0]);
            uint64_t b0 = bp[0], b1 = bp[1], b2 = bp[2], b3 = bp[3];
            float av[8] = {a0.x,a0.y,a0.z,a0.w,a1.x,a1.y,a1.z,a1.w};
            #pragma unroll
            for (int i = 0; i < 8; ++i) {
                uint64_t ad = dup2(av[i]);
                FMA2(acc[i][0], ad, b0); FMA2(acc[i][1], ad, b1);
                FMA2(acc[i][2], ad, b2); FMA2(acc[i][3], ad, b3);
            }
        }
        if (t + 1 < NT) {
            int nxt = 1 - cur;
            As[nxt][akc+0][arow] = rA.x; As[nxt][akc+1][arow] = rA.y;
            As[nxt][akc+2][arow] = rA.z; As[nxt][akc+3][arow] = rA.w;
            *reinterpret_cast<float4*>(&Bs[nxt][brow][bnc]) = rB;
        }
        __syncthreads();
    }

    // column sum-of-squares reduction: each thread owns (brow, bnc..bnc+3)
    *reinterpret_cast<float4*>(&sqs[brow][bnc]) = bsq;
    __syncthreads();

    float invc[8];
    #pragma unroll
    for (int j = 0; j < 8; ++j) {
        int c = nn0 + j;
        float ss = 0.f;
        #pragma unroll
        for (int r = 0; r < 8; ++r) ss += sqs[r][c];
        invc[j] = 1.f / fmaxf(sqrtf(ss), 1e-12f);
    }

    #pragma unroll
    for (int i = 0; i < 8; ++i) {
        int m = m0 + i;
        float ir = g_invrn[n*BATCH + m];
        float v[8];
        #pragma unroll
        for (int j = 0; j < 4; ++j) unpack2(acc[i][j], v[2*j], v[2*j+1]);
        float* op = out2 + (size_t)m*(NBINS*NCLS) + n*NCLS + n0 + nn0;
        if ((n0 + nn0) < NCLS)
            *reinterpret_cast<float4*>(op) =
                make_float4(v[0]*ir*invc[0], v[1]*ir*invc[1], v[2]*ir*invc[2], v[3]*ir*invc[3]);
        if ((n0 + nn0 + 4) < NCLS)
            *reinterpret_cast<float4*>(op + 4) =
                make_float4(v[4]*ir*invc[4], v[5]*ir*invc[5], v[6]*ir*invc[6], v[7]*ir*invc[7]);
    }
}

// =====================================================================
extern "C" void kernel_launch(void* const* d_in, const int* in_sizes, int n_in,
                              void* d_out, int out_size) {
    const float* x     = (const float*)d_in[0];
    const float* Wmask = (const float*)d_in[1];
    const float* Wout  = (const float*)d_in[2];
    const float* FF    = (const float*)d_in[3];
    const float* gamma = (const float*)d_in[4];
    const float* beta  = (const float*)d_in[5];
    const float* fc1d  = (const float*)d_in[6];
    float* out  = (float*)d_out;
    float* out1 = out;                                   // [128,31,256]
    float* out2 = out + (size_t)BATCH*NBINS*OUT;         // [128,31,10000]

    k1_hmap<<<BATCH*TT*8, 512>>>(x);
    k2_mask<<<NB, 512>>>(Wmask);
    k3_wout<<<dim3(2, NBINS, SPLITK), 256>>>(Wout);
    k3e_epi<<<NBINS, 256>>>();
    k4_ff<<<dim3(2, NBINS), 256>>>(FF, out1);
    k5_bn<<<NBINS, 256>>>(out1, gamma, beta);
    k5b_rn<<<NB, 64>>>();
    k6_logits<<<dim3((NCLS + 127) / 128, NBINS), 256>>>(fc1d, out2);
}

// round 4
// speedup vs baseline: 1.1339x; 1.1339x over previous
#include <cuda_runtime.h>
#include <cuda_bf16.h>
#include <cstdint>

// ---------------- problem constants ----------------
#define BATCH 128
#define CH    256
#define TT    30
#define WW    11
#define HW    176
#define NBINS 31
#define RED   16
#define KDIM  4096
#define OUT   256
#define NCLS  10000
#define NB    (NBINS*BATCH)

#define LDT   136   // smem tile row stride in bf16 (128 + 8 pad)
#define TILEB (128*LDT*2)  // 34816 bytes per bf16 tile

// ---------------- scratch ----------------
__device__ float g_p[(size_t)NBINS*BATCH*TT*CH];
__device__ float g_pmax[NBINS*BATCH*CH];
__device__ float g_pooled[(size_t)NBINS*BATCH*KDIM];
__device__ float g_feat[NBINS*BATCH*CH];
__device__ float g_bn[NBINS*BATCH*OUT];
__device__ float g_invrn[NB];

// ---------------- f32x2 helpers (k4) ----------------
__device__ __forceinline__ uint64_t dup2(float v) {
    uint64_t r;
    asm("mov.b64 %0, {%1, %1};" : "=l"(r) : "r"(__float_as_uint(v)));
    return r;
}
#define FMA2(acc, a, b) asm("fma.rn.f32x2 %0, %1, %2, %0;" : "+l"(acc) : "l"(a), "l"(b))
__device__ __forceinline__ void unpack2(uint64_t v, float& lo, float& hi) {
    unsigned a, b;
    asm("mov.b64 {%0, %1}, %2;" : "=r"(a), "=r"(b) : "l"(v));
    lo = __uint_as_float(a); hi = __uint_as_float(b);
}

// ---------------- mma helpers ----------------
__device__ __forceinline__ uint32_t smem_u32(const void* p) {
    uint32_t a;
    asm("{ .reg .u64 t; cvta.to.shared.u64 t, %1; cvt.u32.u64 %0, t; }" : "=r"(a) : "l"(p));
    return a;
}
__device__ __forceinline__ void ldsm4(uint32_t a[4], uint32_t addr) {
    asm volatile("ldmatrix.sync.aligned.m8n8.x4.shared.b16 {%0,%1,%2,%3}, [%4];"
        : "=r"(a[0]),"=r"(a[1]),"=r"(a[2]),"=r"(a[3]) : "r"(addr));
}
__device__ __forceinline__ void ldsm4t(uint32_t a[4], uint32_t addr) {
    asm volatile("ldmatrix.sync.aligned.m8n8.x4.trans.shared.b16 {%0,%1,%2,%3}, [%4];"
        : "=r"(a[0]),"=r"(a[1]),"=r"(a[2]),"=r"(a[3]) : "r"(addr));
}
__device__ __forceinline__ void mma_bf16(float d[4], const uint32_t a[4], uint32_t b0, uint32_t b1) {
    asm volatile("mma.sync.aligned.m16n8k16.row.col.f32.bf16.bf16.f32 "
        "{%0,%1,%2,%3}, {%4,%5,%6,%7}, {%8,%9}, {%0,%1,%2,%3};"
        : "+f"(d[0]),"+f"(d[1]),"+f"(d[2]),"+f"(d[3])
        : "r"(a[0]),"r"(a[1]),"r"(a[2]),"r"(a[3]), "r"(b0),"r"(b1));
}
__device__ __forceinline__ unsigned long long pack4bf(float a, float b, float c, float d) {
    __nv_bfloat162 lo = __floats2bfloat162_rn(a, b);
    __nv_bfloat162 hi = __floats2bfloat162_rn(c, d);
    unsigned l32 = *reinterpret_cast<unsigned*>(&lo);
    unsigned h32 = *reinterpret_cast<unsigned*>(&hi);
    return ((unsigned long long)h32 << 32) | l32;
}

// one 128x128x128 bf16x3 chunk: acc += Ahi*Bhi + Ahi*Blo + Alo*Bhi
// A smem: [m 0..127][k 0..127] row-major (LDT); B smem: [k][n] row-major (LDT).
__device__ __forceinline__ void mma_chunk(uint32_t sAhi, uint32_t sAlo,
                                          uint32_t sBhi, uint32_t sBlo,
                                          int lane, int warp_m, int warp_n,
                                          float acc[2][8][4]) {
    const int l15 = lane & 15;
    const int l16 = (lane >> 4) << 3;
    #pragma unroll
    for (int ks = 0; ks < 8; ++ks) {
        const int k = ks * 16;
        uint32_t ahi[2][4], alo[2][4];
        uint32_t bh[8][2], bl[8][2];
        #pragma unroll
        for (int mi = 0; mi < 2; ++mi) {
            uint32_t ao = ((warp_m + mi*16 + l15)*LDT + k + l16) * 2;
            ldsm4(ahi[mi], sAhi + ao);
            ldsm4(alo[mi], sAlo + ao);
        }
        #pragma unroll
        for (int q = 0; q < 4; ++q) {
            uint32_t bo = ((k + l15)*LDT + warp_n + q*16 + l16) * 2;
            uint32_t r[4];
            ldsm4t(r, sBhi + bo);
            bh[2*q][0] = r[0]; bh[2*q][1] = r[1];
            bh[2*q+1][0] = r[2]; bh[2*q+1][1] = r[3];
            ldsm4t(r, sBlo + bo);
            bl[2*q][0] = r[0]; bl[2*q][1] = r[1];
            bl[2*q+1][0] = r[2]; bl[2*q+1][1] = r[3];
        }
        #pragma unroll
        for (int mi = 0; mi < 2; ++mi) {
            #pragma unroll
            for (int nf = 0; nf < 8; ++nf) {
                mma_bf16(acc[mi][nf], ahi[mi], bh[nf][0], bh[nf][1]);
                mma_bf16(acc[mi][nf], ahi[mi], bl[nf][0], bl[nf][1]);
                mma_bf16(acc[mi][nf], alo[mi], bh[nf][0], bh[nf][1]);
            }
        }
    }
}

// =====================================================================
// K1: horizontal strip pooling.
// =====================================================================
__global__ __launch_bounds__(512) void k1_hmap(const float* __restrict__ x) {
    int bid = blockIdx.x;
    int cg = bid & 7;
    int t  = (bid >> 3) % TT;
    int b  = bid / (TT * 8);

    __shared__ float xs[32][180];
    __shared__ float rsum[32][16];
    __shared__ float rmax[32][16];

    const float* xb = x + (((size_t)b*CH + cg*32)*TT + t) * HW;
    int tid = threadIdx.x;

    for (int idx = tid; idx < 32*44; idx += 512) {
        int c = idx / 44, e = idx % 44;
        float4 v = *reinterpret_cast<const float4*>(xb + (size_t)c*TT*HW + e*4);
        *reinterpret_cast<float4*>(&xs[c][e*4]) = v;
    }
    __syncthreads();
    {
        int c = tid >> 4, h = tid & 15;
        float s = 0.f, m = -1e30f;
        #pragma unroll
        for (int w = 0; w < WW; ++w) {
            float v = xs[c][h*WW + w];
            s += v; m = fmaxf(m, v);
        }
        rsum[c][h] = s; rmax[c][h] = m;
    }
    __syncthreads();

    for (int oi = tid; oi < NBINS*32; oi += 512) {
        int n = oi >> 5;
        int c = oi & 31;
        int start, len;
        if      (n == 0) { start = 0;          len = 16; }
        else if (n < 3)  { start = (n-1)*8;    len = 8;  }
        else if (n < 7)  { start = (n-3)*4;    len = 4;  }
        else if (n < 15) { start = (n-7)*2;    len = 2;  }
        else             { start = n-15;       len = 1;  }
        float s = 0.f, m = -1e30f;
        for (int h = 0; h < len; ++h) {
            s += rsum[c][start+h];
            m = fmaxf(m, rmax[c][start+h]);
        }
        g_p[(((size_t)n*BATCH + b)*TT + t)*CH + cg*32 + c] = s / (float)(len*WW) + m;
    }
}

// =====================================================================
// K2: mask logits + softmax + attention pooling + pmax.
// =====================================================================
__global__ __launch_bounds__(512) void k2_mask(const float* __restrict__ Wmask) {
    int nb = blockIdx.x;
    int n = nb >> 7;
    int b = nb & 127;
    __shared__ float ps[TT][CH];
    __shared__ float wms[CH][RED];
    __shared__ float lg[TT][RED];

    int tid = threadIdx.x;
    const float* pg = g_p + ((size_t)n*BATCH + b)*TT*CH;
    for (int i = tid; i < TT*CH/4; i += 512) {
        float4 v = *reinterpret_cast<const float4*>(pg + i*4);
        *reinterpret_cast<float4*>(&ps[0][0] + i*4) = v;
    }
    const float* wg = Wmask + (size_t)n*CH*RED;
    for (int i = tid; i < CH*RED/4; i += 512) {
        float4 v = *reinterpret_cast<const float4*>(wg + i*4);
        *reinterpret_cast<float4*>(&wms[0][0] + i*4) = v;
    }
    __syncthreads();

    if (tid < TT*RED) {
        int t = tid >> 4, r = tid & 15;
        float acc = 0.f;
        #pragma unroll 8
        for (int c = 0; c < CH; ++c) acc += ps[t][c] * wms[c][r];
        lg[t][r] = acc;
    }
    __syncthreads();

    if (tid < RED) {
        int r = tid;
        float m = -1e30f;
        for (int t = 0; t < TT; ++t) m = fmaxf(m, lg[t][r]);
        float s = 0.f;
        for (int t = 0; t < TT; ++t) { float e = expf(lg[t][r] - m); lg[t][r] = e; s += e; }
        float inv = 1.f / s;
        for (int t = 0; t < TT; ++t) lg[t][r] *= inv;
    }
    __syncthreads();

    {
        int c = tid & 255;
        int rh = tid >> 8;
        float acc[8];
        #pragma unroll
        for (int r = 0; r < 8; ++r) acc[r] = 0.f;
        float pm = -1e30f;
        for (int t = 0; t < TT; ++t) {
            float pv = ps[t][c];
            pm = fmaxf(pm, pv);
            float4 m0 = *reinterpret_cast<const float4*>(&lg[t][rh*8]);
            float4 m1 = *reinterpret_cast<const float4*>(&lg[t][rh*8+4]);
            acc[0] += pv*m0.x; acc[1] += pv*m0.y; acc[2] += pv*m0.z; acc[3] += pv*m0.w;
            acc[4] += pv*m1.x; acc[5] += pv*m1.y; acc[6] += pv*m1.z; acc[7] += pv*m1.w;
        }
        float* pd = g_pooled + ((size_t)n*BATCH + b)*KDIM + c*RED + rh*8;
        *reinterpret_cast<float4*>(pd)     = make_float4(acc[0],acc[1],acc[2],acc[3]);
        *reinterpret_cast<float4*>(pd + 4) = make_float4(acc[4],acc[5],acc[6],acc[7]);
        if (rh == 0) g_pmax[((size_t)n*BATCH + b)*CH + c] = pm;
    }
}

// =====================================================================
// K3 (HMMA bf16x3): feat = pmax + leaky(pooled @ Wout)
// grid (2 Ntiles, NBINS); 128x128 tile; K=4096 in 32 chunks of 128.
// =====================================================================
#define K3_SMEM (4*TILEB)

__global__ __launch_bounds__(256, 1) void k3_mma(const float* __restrict__ Wout) {
    extern __shared__ char smem[];
    const int n  = blockIdx.y;
    const int n0 = blockIdx.x * 128;
    const int tid = threadIdx.x;
    const int lane = tid & 31, wid = tid >> 5;
    const int warp_m = (wid >> 1) * 32, warp_n = (wid & 1) * 64;
    const uint32_t sb = smem_u32(smem);
    const uint32_t sAhi = sb, sAlo = sb + TILEB, sBhi = sb + 2*TILEB, sBlo = sb + 3*TILEB;

    const float* A = g_pooled + (size_t)n*BATCH*KDIM;
    const float* B = Wout + (size_t)n*KDIM*OUT;

    float acc[2][8][4];
    #pragma unroll
    for (int mi = 0; mi < 2; ++mi)
        #pragma unroll
        for (int nf = 0; nf < 8; ++nf)
            #pragma unroll
            for (int j = 0; j < 4; ++j) acc[mi][nf][j] = 0.f;

    const int cg = (tid & 31) * 4;
    const int kr = tid >> 5;

    for (int kc = 0; kc < 32; ++kc) {
        // A chunk: [128 m][128 k]
        for (int i = tid; i < 128*32; i += 256) {
            int row = i >> 5, c4 = (i & 31) * 4;
            float4 v = *reinterpret_cast<const float4*>(A + (size_t)row*KDIM + kc*128 + c4);
            __nv_bfloat16 h0 = __float2bfloat16(v.x), h1 = __float2bfloat16(v.y),
                          h2 = __float2bfloat16(v.z), h3 = __float2bfloat16(v.w);
            int o = (row*LDT + c4) * 2;
            *reinterpret_cast<unsigned long long*>(smem + (sAhi - sb) + o) =
                pack4bf(v.x, v.y, v.z, v.w);
            *reinterpret_cast<unsigned long long*>(smem + (sAlo - sb) + o) =
                pack4bf(v.x - __bfloat162float(h0), v.y - __bfloat162float(h1),
                        v.z - __bfloat162float(h2), v.w - __bfloat162float(h3));
        }
        // B chunk: [128 k][128 n] — same orientation as global
        #pragma unroll 4
        for (int i = 0; i < 16; ++i) {
            int k = kr + i*8;
            float4 v = *reinterpret_cast<const float4*>(B + (size_t)(kc*128 + k)*OUT + n0 + cg);
            __nv_bfloat16 h0 = __float2bfloat16(v.x), h1 = __float2bfloat16(v.y),
                          h2 = __float2bfloat16(v.z), h3 = __float2bfloat16(v.w);
            int o = (k*LDT + cg) * 2;
            *reinterpret_cast<unsigned long long*>(smem + 2*TILEB + o) =
                pack4bf(v.x, v.y, v.z, v.w);
            *reinterpret_cast<unsigned long long*>(smem + 3*TILEB + o) =
                pack4bf(v.x - __bfloat162float(h0), v.y - __bfloat162float(h1),
                        v.z - __bfloat162float(h2), v.w - __bfloat162float(h3));
        }
        __syncthreads();
        mma_chunk(sAhi, sAlo, sBhi, sBlo, lane, warp_m, warp_n, acc);
        __syncthreads();
    }

    // epilogue: leaky + pmax -> g_feat
    const int g = lane >> 2, t2 = (lane & 3) * 2;
    #pragma unroll
    for (int mi = 0; mi < 2; ++mi) {
        #pragma unroll
        for (int nf = 0; nf < 8; ++nf) {
            int col = warp_n + nf*8 + t2;
            #pragma unroll
            for (int h = 0; h < 2; ++h) {
                int row = warp_m + mi*16 + g + h*8;
                float v0 = acc[mi][nf][2*h], v1 = acc[mi][nf][2*h+1];
                v0 = (v0 >= 0.f) ? v0 : 0.01f*v0;
                v1 = (v1 >= 0.f) ? v1 : 0.01f*v1;
                const float2 pm = *reinterpret_cast<const float2*>(
                    g_pmax + ((size_t)n*BATCH + row)*CH + n0 + col);
                *reinterpret_cast<float2*>(
                    g_feat + ((size_t)n*BATCH + row)*CH + n0 + col) =
                    make_float2(v0 + pm.x, v1 + pm.y);
            }
        }
    }
}

// =====================================================================
// K4: outputs = feat @ FForward -> out1 [B, n, O]. FFMA2 (small).
// =====================================================================
__global__ __launch_bounds__(256, 2) void k4_ff(const float* __restrict__ FF, float* __restrict__ out1) {
    int n  = blockIdx.y;
    int n0 = blockIdx.x * 128;
    const float* A = g_feat + (size_t)n*BATCH*CH;
    const float* B = FF + (size_t)n*CH*OUT;

    __shared__ float As[2][8][128];
    __shared__ float Bs[2][8][128];

    int tid = threadIdx.x;
    int arow = tid >> 1, akc = (tid & 1) * 4;
    int brow = tid >> 5, bnc = (tid & 31) * 4;
    int m0 = (tid >> 4) * 8, nn0 = (tid & 15) * 8;

    uint64_t acc[8][4];
    #pragma unroll
    for (int i = 0; i < 8; ++i)
        #pragma unroll
        for (int j = 0; j < 4; ++j) acc[i][j] = 0ULL;

    const int NT = CH / 8;
    float4 rA, rB;
    rA = *reinterpret_cast<const float4*>(A + (size_t)arow*CH + akc);
    rB = *reinterpret_cast<const float4*>(B + (size_t)brow*OUT + n0 + bnc);
    As[0][akc+0][arow] = rA.x; As[0][akc+1][arow] = rA.y;
    As[0][akc+2][arow] = rA.z; As[0][akc+3][arow] = rA.w;
    *reinterpret_cast<float4*>(&Bs[0][brow][bnc]) = rB;
    __syncthreads();

    for (int t = 0; t < NT; ++t) {
        int cur = t & 1;
        if (t + 1 < NT) {
            int k0 = (t+1)*8;
            rA = *reinterpret_cast<const float4*>(A + (size_t)arow*CH + k0 + akc);
            rB = *reinterpret_cast<const float4*>(B + (size_t)(k0 + brow)*OUT + n0 + bnc);
        }
        #pragma unroll
        for (int kk = 0; kk < 8; ++kk) {
            float4 a0 = *reinterpret_cast<const float4*>(&As[cur][kk][m0]);
            float4 a1 = *reinterpret_cast<const float4*>(&As[cur][kk][m0+4]);
            const uint64_t* bp = reinterpret_cast<const uint64_t*>(&Bs[cur][kk][nn0]);
            uint64_t b0 = bp[0], b1 = bp[1], b2 = bp[2], b3 = bp[3];
            float av[8] = {a0.x,a0.y,a0.z,a0.w,a1.x,a1.y,a1.z,a1.w};
            #pragma unroll
            for (int i = 0; i < 8; ++i) {
                uint64_t ad = dup2(av[i]);
                FMA2(acc[i][0], ad, b0); FMA2(acc[i][1], ad, b1);
                FMA2(acc[i][2], ad, b2); FMA2(acc[i][3], ad, b3);
            }
        }
        if (t + 1 < NT) {
            int nxt = 1 - cur;
            As[nxt][akc+0][arow] = rA.x; As[nxt][akc+1][arow] = rA.y;
            As[nxt][akc+2][arow] = rA.z; As[nxt][akc+3][arow] = rA.w;
            *reinterpret_cast<float4*>(&Bs[nxt][brow][bnc]) = rB;
        }
        __syncthreads();
    }

    #pragma unroll
    for (int i = 0; i < 8; ++i) {
        int m = m0 + i;
        float v[8];
        #pragma unroll
        for (int j = 0; j < 4; ++j) unpack2(acc[i][j], v[2*j], v[2*j+1]);
        float* op = out1 + (size_t)m*(NBINS*OUT) + n*OUT + n0 + nn0;
        *reinterpret_cast<float4*>(op)     = make_float4(v[0],v[1],v[2],v[3]);
        *reinterpret_cast<float4*>(op + 4) = make_float4(v[4],v[5],v[6],v[7]);
    }
}

// =====================================================================
// K5: per-bin BatchNorm (two-pass).
// =====================================================================
__global__ __launch_bounds__(256) void k5_bn(const float* __restrict__ out1,
                                             const float* __restrict__ gamma,
                                             const float* __restrict__ beta) {
    int n = blockIdx.x, o = threadIdx.x;
    const float* base = out1 + n*OUT + o;
    const int STR = NBINS*OUT;
    float s = 0.f;
    #pragma unroll 4
    for (int b = 0; b < BATCH; ++b) s += base[(size_t)b*STR];
    float mean = s * (1.f/BATCH);
    float v = 0.f;
    #pragma unroll 4
    for (int b = 0; b < BATCH; ++b) { float d = base[(size_t)b*STR] - mean; v += d*d; }
    v *= (1.f/BATCH);
    float istd = rsqrtf(v + 1e-5f);
    float g = gamma[n*OUT + o], be = beta[n*OUT + o];
    float* bnp = g_bn + (size_t)n*BATCH*OUT + o;
    #pragma unroll 4
    for (int b = 0; b < BATCH; ++b)
        bnp[(size_t)b*OUT] = g * (base[(size_t)b*STR] - mean) * istd + be;
}

__global__ __launch_bounds__(64) void k5b_rn() {
    int nb = blockIdx.x;
    int tid = threadIdx.x;
    const float* r = g_bn + (size_t)nb*OUT;
    float s = 0.f;
    for (int i = tid; i < OUT; i += 64) { float v = r[i]; s += v*v; }
    #pragma unroll
    for (int o = 16; o > 0; o >>= 1) s += __shfl_xor_sync(0xffffffffu, s, o);
    __shared__ float ws[2];
    if ((tid & 31) == 0) ws[tid >> 5] = s;
    __syncthreads();
    if (tid == 0) g_invrn[nb] = 1.f / fmaxf(sqrtf(ws[0] + ws[1]), 1e-12f);
}

// =====================================================================
// K6 (HMMA bf16x3): logits = (bn @ fc1d) * invrow * invcol
// grid (79, NBINS); 128x128 tile; K=256 in 2 chunks of 128.
// Column sumsq fused into B global loads.
// =====================================================================
#define K6_CSQ (4*TILEB)            // 8*128 floats
#define K6_INV (K6_CSQ + 4096)      // 128 floats
#define K6_SMEM (K6_INV + 512)

__global__ __launch_bounds__(256, 1) void k6_mma(const float* __restrict__ fc,
                                                 float* __restrict__ out2) {
    extern __shared__ char smem[];
    const int n  = blockIdx.y;
    const int n0 = blockIdx.x * 128;
    const int tid = threadIdx.x;
    const int lane = tid & 31, wid = tid >> 5;
    const int warp_m = (wid >> 1) * 32, warp_n = (wid & 1) * 64;
    const uint32_t sb = smem_u32(smem);
    const uint32_t sAhi = sb, sAlo = sb + TILEB, sBhi = sb + 2*TILEB, sBlo = sb + 3*TILEB;

    const float* A = g_bn + (size_t)n*BATCH*OUT;
    const float* Bg = fc + (size_t)n*OUT*NCLS;

    float acc[2][8][4];
    #pragma unroll
    for (int mi = 0; mi < 2; ++mi)
        #pragma unroll
        for (int nf = 0; nf < 8; ++nf)
            #pragma unroll
            for (int j = 0; j < 4; ++j) acc[mi][nf][j] = 0.f;

    const int cg = (tid & 31) * 4;
    const int kr = tid >> 5;
    const bool valid = (n0 + cg) < NCLS;     // float4 fully in or out (4 | 10000)
    float sq0 = 0.f, sq1 = 0.f, sq2 = 0.f, sq3 = 0.f;

    for (int kc = 0; kc < 2; ++kc) {
        // A chunk
        for (int i = tid; i < 128*32; i += 256) {
            int row = i >> 5, c4 = (i & 31) * 4;
            float4 v = *reinterpret_cast<const float4*>(A + (size_t)row*OUT + kc*128 + c4);
            __nv_bfloat16 h0 = __float2bfloat16(v.x), h1 = __float2bfloat16(v.y),
                          h2 = __float2bfloat16(v.z), h3 = __float2bfloat16(v.w);
            int o = (row*LDT + c4) * 2;
            *reinterpret_cast<unsigned long long*>(smem + o) =
                pack4bf(v.x, v.y, v.z, v.w);
            *reinterpret_cast<unsigned long long*>(smem + TILEB + o) =
                pack4bf(v.x - __bfloat162float(h0), v.y - __bfloat162float(h1),
                        v.z - __bfloat162float(h2), v.w - __bfloat162float(h3));
        }
        // B chunk + sumsq
        #pragma unroll 4
        for (int i = 0; i < 16; ++i) {
            int k = kr + i*8;
            float4 v = valid ? *reinterpret_cast<const float4*>(
                                   Bg + (size_t)(kc*128 + k)*NCLS + n0 + cg)
                             : make_float4(0.f, 0.f, 0.f, 0.f);
            sq0 += v.x*v.x; sq1 += v.y*v.y; sq2 += v.z*v.z; sq3 += v.w*v.w;
            __nv_bfloat16 h0 = __float2bfloat16(v.x), h1 = __float2bfloat16(v.y),
                          h2 = __float2bfloat16(v.z), h3 = __float2bfloat16(v.w);
            int o = (k*LDT + cg) * 2;
            *reinterpret_cast<unsigned long long*>(smem + 2*TILEB + o) =
                pack4bf(v.x, v.y, v.z, v.w);
            *reinterpret_cast<unsigned long long*>(smem + 3*TILEB + o) =
                pack4bf(v.x - __bfloat162float(h0), v.y - __bfloat162float(h1),
                        v.z - __bfloat162float(h2), v.w - __bfloat162float(h3));
        }
        __syncthreads();
        mma_chunk(sAhi, sAlo, sBhi, sBlo, lane, warp_m, warp_n, acc);
        __syncthreads();
    }

    // column inv-norms
    float* csq = reinterpret_cast<float*>(smem + K6_CSQ);
    *reinterpret_cast<float4*>(csq + kr*128 + cg) = make_float4(sq0, sq1, sq2, sq3);
    __syncthreads();
    float* inv = reinterpret_cast<float*>(smem + K6_INV);
    if (tid < 128) {
        float ss = 0.f;
        #pragma unroll
        for (int r = 0; r < 8; ++r) ss += csq[r*128 + tid];
        inv[tid] = 1.f / fmaxf(sqrtf(ss), 1e-12f);
    }
    __syncthreads();

    // epilogue
    const int g = lane >> 2, t2 = (lane & 3) * 2;
    #pragma unroll
    for (int mi = 0; mi < 2; ++mi) {
        #pragma unroll
        for (int nf = 0; nf < 8; ++nf) {
            int col = warp_n + nf*8 + t2;
            if (n0 + col >= NCLS) continue;
            float ic0 = inv[col], ic1 = inv[col+1];
            #pragma unroll
            for (int h = 0; h < 2; ++h) {
                int row = warp_m + mi*16 + g + h*8;
                float ir = g_invrn[n*BATCH + row];
                *reinterpret_cast<float2*>(
                    out2 + (size_t)row*(NBINS*NCLS) + n*NCLS + n0 + col) =
                    make_float2(acc[mi][nf][2*h]*ir*ic0, acc[mi][nf][2*h+1]*ir*ic1);
            }
        }
    }
}

// =====================================================================
extern "C" void kernel_launch(void* const* d_in, const int* in_sizes, int n_in,
                              void* d_out, int out_size) {
    const float* x     = (const float*)d_in[0];
    const float* Wmask = (const float*)d_in[1];
    const float* Wout  = (const float*)d_in[2];
    const float* FF    = (const float*)d_in[3];
    const float* gamma = (const float*)d_in[4];
    const float* beta  = (const float*)d_in[5];
    const float* fc1d  = (const float*)d_in[6];
    float* out  = (float*)d_out;
    float* out1 = out;                                   // [128,31,256]
    float* out2 = out + (size_t)BATCH*NBINS*OUT;         // [128,31,10000]

    cudaFuncSetAttribute(k3_mma, cudaFuncAttributeMaxDynamicSharedMemorySize, K3_SMEM);
    cudaFuncSetAttribute(k6_mma, cudaFuncAttributeMaxDynamicSharedMemorySize, K6_SMEM);

    k1_hmap<<<BATCH*TT*8, 512>>>(x);
    k2_mask<<<NB, 512>>>(Wmask);
    k3_mma<<<dim3(2, NBINS), 256, K3_SMEM>>>(Wout);
    k4_ff<<<dim3(2, NBINS), 256>>>(FF, out1);
    k5_bn<<<NBINS, 256>>>(out1, gamma, beta);
    k5b_rn<<<NB, 64>>>();
    k6_mma<<<dim3((NCLS + 127) / 128, NBINS), 256, K6_SMEM>>>(fc1d, out2);
}

// round 5
// speedup vs baseline: 1.3528x; 1.1931x over previous
#include <cuda_runtime.h>
#include <cuda_bf16.h>
#include <cstdint>

// ---------------- problem constants ----------------
#define BATCH 128
#define CH    256
#define TT    30
#define WW    11
#define HW    176
#define NBINS 31
#define RED   16
#define KDIM  4096
#define OUT   256
#define NCLS  10000
#define NB    (NBINS*BATCH)

#define LDA   136   // A smem row stride (bf16)
#define LDB   72    // B smem row stride (bf16)

// ---------------- scratch ----------------
__device__ float g_p[(size_t)NBINS*BATCH*TT*CH];
__device__ float g_pmax[NBINS*BATCH*CH];
__device__ __nv_bfloat16 g_pooled_hi[(size_t)NBINS*BATCH*KDIM];
__device__ __nv_bfloat16 g_pooled_lo[(size_t)NBINS*BATCH*KDIM];
__device__ float g_feat[NBINS*BATCH*CH];
__device__ __nv_bfloat16 g_bn_hi[NBINS*BATCH*OUT];
__device__ __nv_bfloat16 g_bn_lo[NBINS*BATCH*OUT];
__device__ float g_invrn[NB];

// ---------------- f32x2 helpers (k4) ----------------
__device__ __forceinline__ uint64_t dup2(float v) {
    uint64_t r;
    asm("mov.b64 %0, {%1, %1};" : "=l"(r) : "r"(__float_as_uint(v)));
    return r;
}
#define FMA2(acc, a, b) asm("fma.rn.f32x2 %0, %1, %2, %0;" : "+l"(acc) : "l"(a), "l"(b))
__device__ __forceinline__ void unpack2(uint64_t v, float& lo, float& hi) {
    unsigned a, b;
    asm("mov.b64 {%0, %1}, %2;" : "=r"(a), "=r"(b) : "l"(v));
    lo = __uint_as_float(a); hi = __uint_as_float(b);
}

// ---------------- mma helpers ----------------
__device__ __forceinline__ uint32_t smem_u32(const void* p) {
    uint32_t a;
    asm("{ .reg .u64 t; cvta.to.shared.u64 t, %1; cvt.u32.u64 %0, t; }" : "=r"(a) : "l"(p));
    return a;
}
__device__ __forceinline__ void ldsm4(uint32_t a[4], uint32_t addr) {
    asm volatile("ldmatrix.sync.aligned.m8n8.x4.shared.b16 {%0,%1,%2,%3}, [%4];"
        : "=r"(a[0]),"=r"(a[1]),"=r"(a[2]),"=r"(a[3]) : "r"(addr));
}
__device__ __forceinline__ void ldsm4t(uint32_t a[4], uint32_t addr) {
    asm volatile("ldmatrix.sync.aligned.m8n8.x4.trans.shared.b16 {%0,%1,%2,%3}, [%4];"
        : "=r"(a[0]),"=r"(a[1]),"=r"(a[2]),"=r"(a[3]) : "r"(addr));
}
__device__ __forceinline__ void mma_bf16(float d[4], const uint32_t a[4], uint32_t b0, uint32_t b1) {
    asm volatile("mma.sync.aligned.m16n8k16.row.col.f32.bf16.bf16.f32 "
        "{%0,%1,%2,%3}, {%4,%5,%6,%7}, {%8,%9}, {%0,%1,%2,%3};"
        : "+f"(d[0]),"+f"(d[1]),"+f"(d[2]),"+f"(d[3])
        : "r"(a[0]),"r"(a[1]),"r"(a[2]),"r"(a[3]), "r"(b0),"r"(b1));
}
__device__ __forceinline__ unsigned long long pack4bf(float a, float b, float c, float d) {
    __nv_bfloat162 lo = __floats2bfloat162_rn(a, b);
    __nv_bfloat162 hi = __floats2bfloat162_rn(c, d);
    unsigned l32 = *reinterpret_cast<unsigned*>(&lo);
    unsigned h32 = *reinterpret_cast<unsigned*>(&hi);
    return ((unsigned long long)h32 << 32) | l32;
}

// bf16x3 tile step over one K=128 chunk: acc += Ahi*Bhi + Ahi*Blo + Alo*Bhi.
// A smem [m][k] stride LDA; B smem [k][n] stride LDB.
template<int MI, int NF>
__device__ __forceinline__ void mma_tile(uint32_t sAhi, uint32_t sAlo,
                                         uint32_t sBhi, uint32_t sBlo,
                                         int lane, int warp_m, int warp_n,
                                         float (&acc)[MI][NF][4]) {
    const int l15 = lane & 15;
    const int l16 = (lane >> 4) << 3;
    #pragma unroll
    for (int ks = 0; ks < 8; ++ks) {
        const int k = ks * 16;
        uint32_t ahi[MI][4], alo[MI][4];
        uint32_t bh[NF][2], bl[NF][2];
        #pragma unroll
        for (int mi = 0; mi < MI; ++mi) {
            uint32_t ao = ((warp_m + mi*16 + l15)*LDA + k + l16) * 2;
            ldsm4(ahi[mi], sAhi + ao);
            ldsm4(alo[mi], sAlo + ao);
        }
        #pragma unroll
        for (int q = 0; q < NF/2; ++q) {
            uint32_t bo = ((k + l15)*LDB + warp_n + q*16 + l16) * 2;
            uint32_t r[4];
            ldsm4t(r, sBhi + bo);
            bh[2*q][0] = r[0]; bh[2*q][1] = r[1];
            bh[2*q+1][0] = r[2]; bh[2*q+1][1] = r[3];
            ldsm4t(r, sBlo + bo);
            bl[2*q][0] = r[0]; bl[2*q][1] = r[1];
            bl[2*q+1][0] = r[2]; bl[2*q+1][1] = r[3];
        }
        #pragma unroll
        for (int mi = 0; mi < MI; ++mi) {
            #pragma unroll
            for (int nf = 0; nf < NF; ++nf) {
                mma_bf16(acc[mi][nf], ahi[mi], bh[nf][0], bh[nf][1]);
                mma_bf16(acc[mi][nf], ahi[mi], bl[nf][0], bl[nf][1]);
                mma_bf16(acc[mi][nf], alo[mi], bh[nf][0], bh[nf][1]);
            }
        }
    }
}

// =====================================================================
// K1: horizontal strip pooling.
// =====================================================================
__global__ __launch_bounds__(512) void k1_hmap(const float* __restrict__ x) {
    int bid = blockIdx.x;
    int cg = bid & 7;
    int t  = (bid >> 3) % TT;
    int b  = bid / (TT * 8);

    __shared__ float xs[32][180];
    __shared__ float rsum[32][16];
    __shared__ float rmax[32][16];

    const float* xb = x + (((size_t)b*CH + cg*32)*TT + t) * HW;
    int tid = threadIdx.x;

    for (int idx = tid; idx < 32*44; idx += 512) {
        int c = idx / 44, e = idx % 44;
        float4 v = *reinterpret_cast<const float4*>(xb + (size_t)c*TT*HW + e*4);
        *reinterpret_cast<float4*>(&xs[c][e*4]) = v;
    }
    __syncthreads();
    {
        int c = tid >> 4, h = tid & 15;
        float s = 0.f, m = -1e30f;
        #pragma unroll
        for (int w = 0; w < WW; ++w) {
            float v = xs[c][h*WW + w];
            s += v; m = fmaxf(m, v);
        }
        rsum[c][h] = s; rmax[c][h] = m;
    }
    __syncthreads();

    for (int oi = tid; oi < NBINS*32; oi += 512) {
        int n = oi >> 5;
        int c = oi & 31;
        int start, len;
        if      (n == 0) { start = 0;          len = 16; }
        else if (n < 3)  { start = (n-1)*8;    len = 8;  }
        else if (n < 7)  { start = (n-3)*4;    len = 4;  }
        else if (n < 15) { start = (n-7)*2;    len = 2;  }
        else             { start = n-15;       len = 1;  }
        float s = 0.f, m = -1e30f;
        for (int h = 0; h < len; ++h) {
            s += rsum[c][start+h];
            m = fmaxf(m, rmax[c][start+h]);
        }
        g_p[(((size_t)n*BATCH + b)*TT + t)*CH + cg*32 + c] = s / (float)(len*WW) + m;
    }
}

// =====================================================================
// K2: mask logits + softmax + attention pooling + pmax.
// Pooled stored directly as bf16 hi/lo (conversion free, values in regs).
// =====================================================================
__global__ __launch_bounds__(512) void k2_mask(const float* __restrict__ Wmask) {
    int nb = blockIdx.x;
    int n = nb >> 7;
    int b = nb & 127;
    __shared__ float ps[TT][CH];
    __shared__ float wms[CH][RED];
    __shared__ float lg[TT][RED];

    int tid = threadIdx.x;
    const float* pg = g_p + ((size_t)n*BATCH + b)*TT*CH;
    for (int i = tid; i < TT*CH/4; i += 512) {
        float4 v = *reinterpret_cast<const float4*>(pg + i*4);
        *reinterpret_cast<float4*>(&ps[0][0] + i*4) = v;
    }
    const float* wg = Wmask + (size_t)n*CH*RED;
    for (int i = tid; i < CH*RED/4; i += 512) {
        float4 v = *reinterpret_cast<const float4*>(wg + i*4);
        *reinterpret_cast<float4*>(&wms[0][0] + i*4) = v;
    }
    __syncthreads();

    if (tid < TT*RED) {
        int t = tid >> 4, r = tid & 15;
        float acc = 0.f;
        #pragma unroll 8
        for (int c = 0; c < CH; ++c) acc += ps[t][c] * wms[c][r];
        lg[t][r] = acc;
    }
    __syncthreads();

    if (tid < RED) {
        int r = tid;
        float m = -1e30f;
        for (int t = 0; t < TT; ++t) m = fmaxf(m, lg[t][r]);
        float s = 0.f;
        for (int t = 0; t < TT; ++t) { float e = expf(lg[t][r] - m); lg[t][r] = e; s += e; }
        float inv = 1.f / s;
        for (int t = 0; t < TT; ++t) lg[t][r] *= inv;
    }
    __syncthreads();

    {
        int c = tid & 255;
        int rh = tid >> 8;
        float acc[8];
        #pragma unroll
        for (int r = 0; r < 8; ++r) acc[r] = 0.f;
        float pm = -1e30f;
        for (int t = 0; t < TT; ++t) {
            float pv = ps[t][c];
            pm = fmaxf(pm, pv);
            float4 m0 = *reinterpret_cast<const float4*>(&lg[t][rh*8]);
            float4 m1 = *reinterpret_cast<const float4*>(&lg[t][rh*8+4]);
            acc[0] += pv*m0.x; acc[1] += pv*m0.y; acc[2] += pv*m0.z; acc[3] += pv*m0.w;
            acc[4] += pv*m1.x; acc[5] += pv*m1.y; acc[6] += pv*m1.z; acc[7] += pv*m1.w;
        }
        size_t base = ((size_t)n*BATCH + b)*KDIM + c*RED + rh*8;
        float hi[8], lo[8];
        #pragma unroll
        for (int r = 0; r < 8; ++r) {
            __nv_bfloat16 h = __float2bfloat16(acc[r]);
            hi[r] = acc[r];                 // pack4bf rounds to bf16
            lo[r] = acc[r] - __bfloat162float(h);
        }
        unsigned long long* dh = reinterpret_cast<unsigned long long*>(g_pooled_hi + base);
        unsigned long long* dl = reinterpret_cast<unsigned long long*>(g_pooled_lo + base);
        dh[0] = pack4bf(hi[0],hi[1],hi[2],hi[3]); dh[1] = pack4bf(hi[4],hi[5],hi[6],hi[7]);
        dl[0] = pack4bf(lo[0],lo[1],lo[2],lo[3]); dl[1] = pack4bf(lo[4],lo[5],lo[6],lo[7]);
        if (rh == 0) g_pmax[((size_t)n*BATCH + b)*CH + c] = pm;
    }
}

// =====================================================================
// K3 (HMMA bf16x3): feat = pmax + leaky(pooled @ Wout)
// 64x64 tiles, grid (4 N, 2 M, 31 bins) = 248 CTAs, occ 3.
// A from precomputed bf16 hi/lo; B (Wout) converted inline.
// =====================================================================
#define K3_ATILE (64*LDA*2)          // 17408
#define K3_BTILE (128*LDB*2)         // 18432
#define K3_SMEM  (2*K3_ATILE + 2*K3_BTILE)   // 71680

__global__ __launch_bounds__(256, 3) void k3_mma(const float* __restrict__ Wout) {
    extern __shared__ char smem[];
    const int n  = blockIdx.z;
    const int n0 = blockIdx.x * 64;
    const int m0 = blockIdx.y * 64;
    const int tid = threadIdx.x;
    const int lane = tid & 31, wid = tid >> 5;
    const int warp_m = (wid >> 2) * 32, warp_n = (wid & 3) * 16;
    const uint32_t sb = smem_u32(smem);
    const uint32_t sAhi = sb, sAlo = sb + K3_ATILE;
    const uint32_t sBhi = sb + 2*K3_ATILE, sBlo = sBhi + K3_BTILE;

    const __nv_bfloat16* Ah = g_pooled_hi + ((size_t)n*BATCH + m0)*KDIM;
    const __nv_bfloat16* Al = g_pooled_lo + ((size_t)n*BATCH + m0)*KDIM;
    const float* B = Wout + (size_t)n*KDIM*OUT;

    float acc[2][2][4];
    #pragma unroll
    for (int mi = 0; mi < 2; ++mi)
        #pragma unroll
        for (int nf = 0; nf < 2; ++nf)
            #pragma unroll
            for (int j = 0; j < 4; ++j) acc[mi][nf][j] = 0.f;

    const int cg = (tid & 15) * 4;     // B col group
    const int kr = tid >> 4;           // B row base (0..15)

    for (int kc = 0; kc < 32; ++kc) {
        // A chunk [64 m][128 k] bf16 copies
        #pragma unroll
        for (int i = 0; i < 4; ++i) {
            int idx = tid + i*256;
            int row = idx >> 4, c8 = (idx & 15) * 8;
            uint4 vh = *reinterpret_cast<const uint4*>(Ah + (size_t)row*KDIM + kc*128 + c8);
            uint4 vl = *reinterpret_cast<const uint4*>(Al + (size_t)row*KDIM + kc*128 + c8);
            int o = (row*LDA + c8) * 2;
            *reinterpret_cast<uint4*>(smem + o) = vh;
            *reinterpret_cast<uint4*>(smem + K3_ATILE + o) = vl;
        }
        // B chunk [128 k][64 n] fp32 -> hi/lo bf16
        #pragma unroll 4
        for (int i = 0; i < 8; ++i) {
            int k = kr + i*16;
            float4 v = *reinterpret_cast<const float4*>(B + (size_t)(kc*128 + k)*OUT + n0 + cg);
            __nv_bfloat16 h0 = __float2bfloat16(v.x), h1 = __float2bfloat16(v.y),
                          h2 = __float2bfloat16(v.z), h3 = __float2bfloat16(v.w);
            int o = (k*LDB + cg) * 2;
            *reinterpret_cast<unsigned long long*>(smem + 2*K3_ATILE + o) =
                pack4bf(v.x, v.y, v.z, v.w);
            *reinterpret_cast<unsigned long long*>(smem + 2*K3_ATILE + K3_BTILE + o) =
                pack4bf(v.x - __bfloat162float(h0), v.y - __bfloat162float(h1),
                        v.z - __bfloat162float(h2), v.w - __bfloat162float(h3));
        }
        __syncthreads();
        mma_tile<2,2>(sAhi, sAlo, sBhi, sBlo, lane, warp_m, warp_n, acc);
        __syncthreads();
    }

    // epilogue: leaky + pmax -> g_feat
    const int g = lane >> 2, t2 = (lane & 3) * 2;
    #pragma unroll
    for (int mi = 0; mi < 2; ++mi) {
        #pragma unroll
        for (int nf = 0; nf < 2; ++nf) {
            int col = warp_n + nf*8 + t2;
            #pragma unroll
            for (int h = 0; h < 2; ++h) {
                int row = m0 + warp_m + mi*16 + g + h*8;
                float v0 = acc[mi][nf][2*h], v1 = acc[mi][nf][2*h+1];
                v0 = (v0 >= 0.f) ? v0 : 0.01f*v0;
                v1 = (v1 >= 0.f) ? v1 : 0.01f*v1;
                const float2 pm = *reinterpret_cast<const float2*>(
                    g_pmax + ((size_t)n*BATCH + row)*CH + n0 + col);
                *reinterpret_cast<float2*>(
                    g_feat + ((size_t)n*BATCH + row)*CH + n0 + col) =
                    make_float2(v0 + pm.x, v1 + pm.y);
            }
        }
    }
}

// =====================================================================
// K4: outputs = feat @ FForward -> out1 [B, n, O]. FFMA2 (small).
// =====================================================================
__global__ __launch_bounds__(256, 2) void k4_ff(const float* __restrict__ FF, float* __restrict__ out1) {
    int n  = blockIdx.y;
    int n0 = blockIdx.x * 128;
    const float* A = g_feat + (size_t)n*BATCH*CH;
    const float* B = FF + (size_t)n*CH*OUT;

    __shared__ float As[2][8][128];
    __shared__ float Bs[2][8][128];

    int tid = threadIdx.x;
    int arow = tid >> 1, akc = (tid & 1) * 4;
    int brow = tid >> 5, bnc = (tid & 31) * 4;
    int m0 = (tid >> 4) * 8, nn0 = (tid & 15) * 8;

    uint64_t acc[8][4];
    #pragma unroll
    for (int i = 0; i < 8; ++i)
        #pragma unroll
        for (int j = 0; j < 4; ++j) acc[i][j] = 0ULL;

    const int NT = CH / 8;
    float4 rA, rB;
    rA = *reinterpret_cast<const float4*>(A + (size_t)arow*CH + akc);
    rB = *reinterpret_cast<const float4*>(B + (size_t)brow*OUT + n0 + bnc);
    As[0][akc+0][arow] = rA.x; As[0][akc+1][arow] = rA.y;
    As[0][akc+2][arow] = rA.z; As[0][akc+3][arow] = rA.w;
    *reinterpret_cast<float4*>(&Bs[0][brow][bnc]) = rB;
    __syncthreads();

    for (int t = 0; t < NT; ++t) {
        int cur = t & 1;
        if (t + 1 < NT) {
            int k0 = (t+1)*8;
            rA = *reinterpret_cast<const float4*>(A + (size_t)arow*CH + k0 + akc);
            rB = *reinterpret_cast<const float4*>(B + (size_t)(k0 + brow)*OUT + n0 + bnc);
        }
        #pragma unroll
        for (int kk = 0; kk < 8; ++kk) {
            float4 a0 = *reinterpret_cast<const float4*>(&As[cur][kk][m0]);
            float4 a1 = *reinterpret_cast<const float4*>(&As[cur][kk][m0+4]);
            const uint64_t* bp = reinterpret_cast<const uint64_t*>(&Bs[cur][kk][nn0]);
            uint64_t b0 = bp[0], b1 = bp[1], b2 = bp[2], b3 = bp[3];
            float av[8] = {a0.x,a0.y,a0.z,a0.w,a1.x,a1.y,a1.z,a1.w};
            #pragma unroll
            for (int i = 0; i < 8; ++i) {
                uint64_t ad = dup2(av[i]);
                FMA2(acc[i][0], ad, b0); FMA2(acc[i][1], ad, b1);
                FMA2(acc[i][2], ad, b2); FMA2(acc[i][3], ad, b3);
            }
        }
        if (t + 1 < NT) {
            int nxt = 1 - cur;
            As[nxt][akc+0][arow] = rA.x; As[nxt][akc+1][arow] = rA.y;
            As[nxt][akc+2][arow] = rA.z; As[nxt][akc+3][arow] = rA.w;
            *reinterpret_cast<float4*>(&Bs[nxt][brow][bnc]) = rB;
        }
        __syncthreads();
    }

    #pragma unroll
    for (int i = 0; i < 8; ++i) {
        int m = m0 + i;
        float v[8];
        #pragma unroll
        for (int j = 0; j < 4; ++j) unpack2(acc[i][j], v[2*j], v[2*j+1]);
        float* op = out1 + (size_t)m*(NBINS*OUT) + n*OUT + n0 + nn0;
        *reinterpret_cast<float4*>(op)     = make_float4(v[0],v[1],v[2],v[3]);
        *reinterpret_cast<float4*>(op + 4) = make_float4(v[4],v[5],v[6],v[7]);
    }
}

// =====================================================================
// K5: per-bin BatchNorm; outputs bn as bf16 hi/lo (feeds k6 directly).
// =====================================================================
__global__ __launch_bounds__(256) void k5_bn(const float* __restrict__ out1,
                                             const float* __restrict__ gamma,
                                             const float* __restrict__ beta) {
    int n = blockIdx.x, o = threadIdx.x;
    const float* base = out1 + n*OUT + o;
    const int STR = NBINS*OUT;
    float s = 0.f;
    #pragma unroll 4
    for (int b = 0; b < BATCH; ++b) s += base[(size_t)b*STR];
    float mean = s * (1.f/BATCH);
    float v = 0.f;
    #pragma unroll 4
    for (int b = 0; b < BATCH; ++b) { float d = base[(size_t)b*STR] - mean; v += d*d; }
    v *= (1.f/BATCH);
    float istd = rsqrtf(v + 1e-5f);
    float g = gamma[n*OUT + o], be = beta[n*OUT + o];
    __nv_bfloat16* bh = g_bn_hi + (size_t)n*BATCH*OUT + o;
    __nv_bfloat16* bl = g_bn_lo + (size_t)n*BATCH*OUT + o;
    #pragma unroll 4
    for (int b = 0; b < BATCH; ++b) {
        float val = g * (base[(size_t)b*STR] - mean) * istd + be;
        __nv_bfloat16 h = __float2bfloat16(val);
        bh[(size_t)b*OUT] = h;
        bl[(size_t)b*OUT] = __float2bfloat16(val - __bfloat162float(h));
    }
}

__global__ __launch_bounds__(64) void k5b_rn() {
    int nb = blockIdx.x;
    int tid = threadIdx.x;
    const __nv_bfloat16* rh = g_bn_hi + (size_t)nb*OUT;
    const __nv_bfloat16* rl = g_bn_lo + (size_t)nb*OUT;
    float s = 0.f;
    for (int i = tid; i < OUT; i += 64) {
        float v = __bfloat162float(rh[i]) + __bfloat162float(rl[i]);
        s += v*v;
    }
    #pragma unroll
    for (int o = 16; o > 0; o >>= 1) s += __shfl_xor_sync(0xffffffffu, s, o);
    __shared__ float ws[2];
    if ((tid & 31) == 0) ws[tid >> 5] = s;
    __syncthreads();
    if (tid == 0) g_invrn[nb] = 1.f / fmaxf(sqrtf(ws[0] + ws[1]), 1e-12f);
}

// =====================================================================
// K6 (HMMA bf16x3): logits = (bn @ fc1d) * invrow * invcol
// 128x64 tiles, grid (157, 31) = 4867 CTAs, occ 2.
// A from precomputed bf16 hi/lo; B (fc1d) converted inline + col sumsq.
// =====================================================================
#define K6_ATILE (128*LDA*2)          // 34816
#define K6_BTILE (128*LDB*2)          // 18432
#define K6_CSQ   (2*K6_ATILE + 2*K6_BTILE)   // 106496
#define K6_INV   (K6_CSQ + 16*64*4)          // 110592
#define K6_SMEM  (K6_INV + 64*4)             // 110848

__global__ __launch_bounds__(256, 2) void k6_mma(const float* __restrict__ fc,
                                                 float* __restrict__ out2) {
    extern __shared__ char smem[];
    const int n  = blockIdx.y;
    const int n0 = blockIdx.x * 64;
    const int tid = threadIdx.x;
    const int lane = tid & 31, wid = tid >> 5;
    const int warp_m = (wid >> 1) * 32, warp_n = (wid & 1) * 32;
    const uint32_t sb = smem_u32(smem);
    const uint32_t sAhi = sb, sAlo = sb + K6_ATILE;
    const uint32_t sBhi = sb + 2*K6_ATILE, sBlo = sBhi + K6_BTILE;

    const __nv_bfloat16* Ah = g_bn_hi + (size_t)n*BATCH*OUT;
    const __nv_bfloat16* Al = g_bn_lo + (size_t)n*BATCH*OUT;
    const float* Bg = fc + (size_t)n*OUT*NCLS;

    float acc[2][4][4];
    #pragma unroll
    for (int mi = 0; mi < 2; ++mi)
        #pragma unroll
        for (int nf = 0; nf < 4; ++nf)
            #pragma unroll
            for (int j = 0; j < 4; ++j) acc[mi][nf][j] = 0.f;

    const int cg = (tid & 15) * 4;
    const int kr = tid >> 4;
    const bool valid = (n0 + cg) < NCLS;
    float sq0 = 0.f, sq1 = 0.f, sq2 = 0.f, sq3 = 0.f;

    for (int kc = 0; kc < 2; ++kc) {
        // A chunk [128 m][128 k] bf16 copies
        #pragma unroll
        for (int i = 0; i < 8; ++i) {
            int idx = tid + i*256;
            int row = idx >> 4, c8 = (idx & 15) * 8;
            uint4 vh = *reinterpret_cast<const uint4*>(Ah + (size_t)row*OUT + kc*128 + c8);
            uint4 vl = *reinterpret_cast<const uint4*>(Al + (size_t)row*OUT + kc*128 + c8);
            int o = (row*LDA + c8) * 2;
            *reinterpret_cast<uint4*>(smem + o) = vh;
            *reinterpret_cast<uint4*>(smem + K6_ATILE + o) = vl;
        }
        // B chunk [128 k][64 n] fp32 -> hi/lo bf16, + sumsq
        #pragma unroll 4
        for (int i = 0; i < 8; ++i) {
            int k = kr + i*16;
            float4 v = valid ? *reinterpret_cast<const float4*>(
                                   Bg + (size_t)(kc*128 + k)*NCLS + n0 + cg)
                             : make_float4(0.f, 0.f, 0.f, 0.f);
            sq0 += v.x*v.x; sq1 += v.y*v.y; sq2 += v.z*v.z; sq3 += v.w*v.w;
            __nv_bfloat16 h0 = __float2bfloat16(v.x), h1 = __float2bfloat16(v.y),
                          h2 = __float2bfloat16(v.z), h3 = __float2bfloat16(v.w);
            int o = (k*LDB + cg) * 2;
            *reinterpret_cast<unsigned long long*>(smem + 2*K6_ATILE + o) =
                pack4bf(v.x, v.y, v.z, v.w);
            *reinterpret_cast<unsigned long long*>(smem + 2*K6_ATILE + K6_BTILE + o) =
                pack4bf(v.x - __bfloat162float(h0), v.y - __bfloat162float(h1),
                        v.z - __bfloat162float(h2), v.w - __bfloat162float(h3));
        }
        __syncthreads();
        mma_tile<2,4>(sAhi, sAlo, sBhi, sBlo, lane, warp_m, warp_n, acc);
        __syncthreads();
    }

    // column inv-norms
    float* csq = reinterpret_cast<float*>(smem + K6_CSQ);
    *reinterpret_cast<float4*>(csq + kr*64 + cg) = make_float4(sq0, sq1, sq2, sq3);
    __syncthreads();
    float* inv = reinterpret_cast<float*>(smem + K6_INV);
    if (tid < 64) {
        float ss = 0.f;
        #pragma unroll
        for (int r = 0; r < 16; ++r) ss += csq[r*64 + tid];
        inv[tid] = 1.f / fmaxf(sqrtf(ss), 1e-12f);
    }
    __syncthreads();

    // epilogue
    const int g = lane >> 2, t2 = (lane & 3) * 2;
    #pragma unroll
    for (int mi = 0; mi < 2; ++mi) {
        #pragma unroll
        for (int nf = 0; nf < 4; ++nf) {
            int col = warp_n + nf*8 + t2;
            if (n0 + col >= NCLS) continue;
            float ic0 = inv[col], ic1 = inv[col+1];
            #pragma unroll
            for (int h = 0; h < 2; ++h) {
                int row = warp_m + mi*16 + g + h*8;
                float ir = g_invrn[n*BATCH + row];
                *reinterpret_cast<float2*>(
                    out2 + (size_t)row*(NBINS*NCLS) + n*NCLS + n0 + col) =
                    make_float2(acc[mi][nf][2*h]*ir*ic0, acc[mi][nf][2*h+1]*ir*ic1);
            }
        }
    }
}

// =====================================================================
extern "C" void kernel_launch(void* const* d_in, const int* in_sizes, int n_in,
                              void* d_out, int out_size) {
    const float* x     = (const float*)d_in[0];
    const float* Wmask = (const float*)d_in[1];
    const float* Wout  = (const float*)d_in[2];
    const float* FF    = (const float*)d_in[3];
    const float* gamma = (const float*)d_in[4];
    const float* beta  = (const float*)d_in[5];
    const float* fc1d  = (const float*)d_in[6];
    float* out  = (float*)d_out;
    float* out1 = out;                                   // [128,31,256]
    float* out2 = out + (size_t)BATCH*NBINS*OUT;         // [128,31,10000]

    cudaFuncSetAttribute(k3_mma, cudaFuncAttributeMaxDynamicSharedMemorySize, K3_SMEM);
    cudaFuncSetAttribute(k6_mma, cudaFuncAttributeMaxDynamicSharedMemorySize, K6_SMEM);

    k1_hmap<<<BATCH*TT*8, 512>>>(x);
    k2_mask<<<NB, 512>>>(Wmask);
    k3_mma<<<dim3(4, 2, NBINS), 256, K3_SMEM>>>(Wout);
    k4_ff<<<dim3(2, NBINS), 256>>>(FF, out1);
    k5_bn<<<NBINS, 256>>>(out1, gamma, beta);
    k5b_rn<<<NB, 64>>>();
    k6_mma<<<dim3((NCLS + 63) / 64, NBINS), 256, K6_SMEM>>>(fc1d, out2);
}

// round 6
// speedup vs baseline: 1.5360x; 1.1354x over previous
#include <cuda_runtime.h>
#include <cuda_bf16.h>
#include <cstdint>

// ---------------- problem constants ----------------
#define BATCH 128
#define CH    256
#define TT    30
#define WW    11
#define HW    176
#define NBINS 31
#define RED   16
#define KDIM  4096
#define OUT   256
#define NCLS  10000
#define NB    (NBINS*BATCH)

#define LDA   136   // A smem row stride (bf16)
#define LDB   72    // B smem row stride (bf16)

// ---------------- scratch ----------------
__device__ float g_p[(size_t)NBINS*BATCH*TT*CH];
__device__ float g_pmax[NBINS*BATCH*CH];
__device__ __nv_bfloat16 g_pooled_hi[(size_t)NBINS*BATCH*KDIM];
__device__ __nv_bfloat16 g_pooled_lo[(size_t)NBINS*BATCH*KDIM];
__device__ float g_feat[NBINS*BATCH*CH];
__device__ __nv_bfloat16 g_bn_hi[NBINS*BATCH*OUT];
__device__ __nv_bfloat16 g_bn_lo[NBINS*BATCH*OUT];
__device__ float g_invrn[NB];
__device__ float g_part[(size_t)2*NBINS*BATCH*OUT];

// ---------------- f32x2 helpers (k4) ----------------
__device__ __forceinline__ uint64_t dup2(float v) {
    uint64_t r;
    asm("mov.b64 %0, {%1, %1};" : "=l"(r) : "r"(__float_as_uint(v)));
    return r;
}
#define FMA2(acc, a, b) asm("fma.rn.f32x2 %0, %1, %2, %0;" : "+l"(acc) : "l"(a), "l"(b))
__device__ __forceinline__ void unpack2(uint64_t v, float& lo, float& hi) {
    unsigned a, b;
    asm("mov.b64 {%0, %1}, %2;" : "=r"(a), "=r"(b) : "l"(v));
    lo = __uint_as_float(a); hi = __uint_as_float(b);
}

// ---------------- mma / async helpers ----------------
__device__ __forceinline__ uint32_t smem_u32(const void* p) {
    uint32_t a;
    asm("{ .reg .u64 t; cvta.to.shared.u64 t, %1; cvt.u32.u64 %0, t; }" : "=r"(a) : "l"(p));
    return a;
}
__device__ __forceinline__ void cpa16(uint32_t dst, const void* src) {
    asm volatile("cp.async.cg.shared.global [%0], [%1], 16;" :: "r"(dst), "l"(src));
}
#define CPA_COMMIT() asm volatile("cp.async.commit_group;" ::: "memory")
#define CPA_WAIT0()  asm volatile("cp.async.wait_group 0;" ::: "memory")

__device__ __forceinline__ void ldsm4(uint32_t a[4], uint32_t addr) {
    asm volatile("ldmatrix.sync.aligned.m8n8.x4.shared.b16 {%0,%1,%2,%3}, [%4];"
        : "=r"(a[0]),"=r"(a[1]),"=r"(a[2]),"=r"(a[3]) : "r"(addr));
}
__device__ __forceinline__ void ldsm4t(uint32_t a[4], uint32_t addr) {
    asm volatile("ldmatrix.sync.aligned.m8n8.x4.trans.shared.b16 {%0,%1,%2,%3}, [%4];"
        : "=r"(a[0]),"=r"(a[1]),"=r"(a[2]),"=r"(a[3]) : "r"(addr));
}
__device__ __forceinline__ void mma_bf16(float d[4], const uint32_t a[4], uint32_t b0, uint32_t b1) {
    asm volatile("mma.sync.aligned.m16n8k16.row.col.f32.bf16.bf16.f32 "
        "{%0,%1,%2,%3}, {%4,%5,%6,%7}, {%8,%9}, {%0,%1,%2,%3};"
        : "+f"(d[0]),"+f"(d[1]),"+f"(d[2]),"+f"(d[3])
        : "r"(a[0]),"r"(a[1]),"r"(a[2]),"r"(a[3]), "r"(b0),"r"(b1));
}
__device__ __forceinline__ unsigned long long pack4bf(float a, float b, float c, float d) {
    __nv_bfloat162 lo = __floats2bfloat162_rn(a, b);
    __nv_bfloat162 hi = __floats2bfloat162_rn(c, d);
    unsigned l32 = *reinterpret_cast<unsigned*>(&lo);
    unsigned h32 = *reinterpret_cast<unsigned*>(&hi);
    return ((unsigned long long)h32 << 32) | l32;
}

// bf16x3 tile step over one K=128 chunk: acc += Ahi*Bhi + Ahi*Blo + Alo*Bhi.
template<int MI, int NF>
__device__ __forceinline__ void mma_tile(uint32_t sAhi, uint32_t sAlo,
                                         uint32_t sBhi, uint32_t sBlo,
                                         int lane, int warp_m, int warp_n,
                                         float (&acc)[MI][NF][4]) {
    const int l15 = lane & 15;
    const int l16 = (lane >> 4) << 3;
    #pragma unroll
    for (int ks = 0; ks < 8; ++ks) {
        const int k = ks * 16;
        uint32_t ahi[MI][4], alo[MI][4];
        uint32_t bh[NF][2], bl[NF][2];
        #pragma unroll
        for (int mi = 0; mi < MI; ++mi) {
            uint32_t ao = ((warp_m + mi*16 + l15)*LDA + k + l16) * 2;
            ldsm4(ahi[mi], sAhi + ao);
            ldsm4(alo[mi], sAlo + ao);
        }
        #pragma unroll
        for (int q = 0; q < NF/2; ++q) {
            uint32_t bo = ((k + l15)*LDB + warp_n + q*16 + l16) * 2;
            uint32_t r[4];
            ldsm4t(r, sBhi + bo);
            bh[2*q][0] = r[0]; bh[2*q][1] = r[1];
            bh[2*q+1][0] = r[2]; bh[2*q+1][1] = r[3];
            ldsm4t(r, sBlo + bo);
            bl[2*q][0] = r[0]; bl[2*q][1] = r[1];
            bl[2*q+1][0] = r[2]; bl[2*q+1][1] = r[3];
        }
        #pragma unroll
        for (int mi = 0; mi < MI; ++mi) {
            #pragma unroll
            for (int nf = 0; nf < NF; ++nf) {
                mma_bf16(acc[mi][nf], ahi[mi], bh[nf][0], bh[nf][1]);
                mma_bf16(acc[mi][nf], ahi[mi], bl[nf][0], bl[nf][1]);
                mma_bf16(acc[mi][nf], alo[mi], bh[nf][0], bh[nf][1]);
            }
        }
    }
}

// =====================================================================
// K1: horizontal strip pooling.
// =====================================================================
__global__ __launch_bounds__(512) void k1_hmap(const float* __restrict__ x) {
    int bid = blockIdx.x;
    int cg = bid & 7;
    int t  = (bid >> 3) % TT;
    int b  = bid / (TT * 8);

    __shared__ float xs[32][180];
    __shared__ float rsum[32][16];
    __shared__ float rmax[32][16];

    const float* xb = x + (((size_t)b*CH + cg*32)*TT + t) * HW;
    int tid = threadIdx.x;

    for (int idx = tid; idx < 32*44; idx += 512) {
        int c = idx / 44, e = idx % 44;
        float4 v = *reinterpret_cast<const float4*>(xb + (size_t)c*TT*HW + e*4);
        *reinterpret_cast<float4*>(&xs[c][e*4]) = v;
    }
    __syncthreads();
    {
        int c = tid >> 4, h = tid & 15;
        float s = 0.f, m = -1e30f;
        #pragma unroll
        for (int w = 0; w < WW; ++w) {
            float v = xs[c][h*WW + w];
            s += v; m = fmaxf(m, v);
        }
        rsum[c][h] = s; rmax[c][h] = m;
    }
    __syncthreads();

    for (int oi = tid; oi < NBINS*32; oi += 512) {
        int n = oi >> 5;
        int c = oi & 31;
        int start, len;
        if      (n == 0) { start = 0;          len = 16; }
        else if (n < 3)  { start = (n-1)*8;    len = 8;  }
        else if (n < 7)  { start = (n-3)*4;    len = 4;  }
        else if (n < 15) { start = (n-7)*2;    len = 2;  }
        else             { start = n-15;       len = 1;  }
        float s = 0.f, m = -1e30f;
        for (int h = 0; h < len; ++h) {
            s += rsum[c][start+h];
            m = fmaxf(m, rmax[c][start+h]);
        }
        g_p[(((size_t)n*BATCH + b)*TT + t)*CH + cg*32 + c] = s / (float)(len*WW) + m;
    }
}

// =====================================================================
// K2: mask logits + softmax + attention pooling + pmax.
// =====================================================================
__global__ __launch_bounds__(512) void k2_mask(const float* __restrict__ Wmask) {
    int nb = blockIdx.x;
    int n = nb >> 7;
    int b = nb & 127;
    __shared__ float ps[TT][CH];
    __shared__ float wms[CH][RED];
    __shared__ float lg[TT][RED];

    int tid = threadIdx.x;
    const float* pg = g_p + ((size_t)n*BATCH + b)*TT*CH;
    for (int i = tid; i < TT*CH/4; i += 512) {
        float4 v = *reinterpret_cast<const float4*>(pg + i*4);
        *reinterpret_cast<float4*>(&ps[0][0] + i*4) = v;
    }
    const float* wg = Wmask + (size_t)n*CH*RED;
    for (int i = tid; i < CH*RED/4; i += 512) {
        float4 v = *reinterpret_cast<const float4*>(wg + i*4);
        *reinterpret_cast<float4*>(&wms[0][0] + i*4) = v;
    }
    __syncthreads();

    if (tid < TT*RED) {
        int t = tid >> 4, r = tid & 15;
        float acc = 0.f;
        #pragma unroll 8
        for (int c = 0; c < CH; ++c) acc += ps[t][c] * wms[c][r];
        lg[t][r] = acc;
    }
    __syncthreads();

    if (tid < RED) {
        int r = tid;
        float m = -1e30f;
        for (int t = 0; t < TT; ++t) m = fmaxf(m, lg[t][r]);
        float s = 0.f;
        for (int t = 0; t < TT; ++t) { float e = expf(lg[t][r] - m); lg[t][r] = e; s += e; }
        float inv = 1.f / s;
        for (int t = 0; t < TT; ++t) lg[t][r] *= inv;
    }
    __syncthreads();

    {
        int c = tid & 255;
        int rh = tid >> 8;
        float acc[8];
        #pragma unroll
        for (int r = 0; r < 8; ++r) acc[r] = 0.f;
        float pm = -1e30f;
        for (int t = 0; t < TT; ++t) {
            float pv = ps[t][c];
            pm = fmaxf(pm, pv);
            float4 m0 = *reinterpret_cast<const float4*>(&lg[t][rh*8]);
            float4 m1 = *reinterpret_cast<const float4*>(&lg[t][rh*8+4]);
            acc[0] += pv*m0.x; acc[1] += pv*m0.y; acc[2] += pv*m0.z; acc[3] += pv*m0.w;
            acc[4] += pv*m1.x; acc[5] += pv*m1.y; acc[6] += pv*m1.z; acc[7] += pv*m1.w;
        }
        size_t base = ((size_t)n*BATCH + b)*KDIM + c*RED + rh*8;
        float hi[8], lo[8];
        #pragma unroll
        for (int r = 0; r < 8; ++r) {
            __nv_bfloat16 h = __float2bfloat16(acc[r]);
            hi[r] = acc[r];                 // pack4bf rounds to bf16
            lo[r] = acc[r] - __bfloat162float(h);
        }
        unsigned long long* dh = reinterpret_cast<unsigned long long*>(g_pooled_hi + base);
        unsigned long long* dl = reinterpret_cast<unsigned long long*>(g_pooled_lo + base);
        dh[0] = pack4bf(hi[0],hi[1],hi[2],hi[3]); dh[1] = pack4bf(hi[4],hi[5],hi[6],hi[7]);
        dl[0] = pack4bf(lo[0],lo[1],lo[2],lo[3]); dl[1] = pack4bf(lo[4],lo[5],lo[6],lo[7]);
        if (rh == 0) g_pmax[((size_t)n*BATCH + b)*CH + c] = pm;
    }
}

// =====================================================================
// K3 (HMMA bf16x3, split-K=2, pipelined): partial = pooled @ Wout
// BM=128, BN=64. grid (4 N, NBINS, 2 Ksplit) = 248 CTAs, occ 2.
// cp.async for A (bf16 hi/lo), register-prefetch for B (fp32 -> cvt).
// =====================================================================
#define K3_ATILE (128*LDA*2)          // 34816
#define K3_BTILE (128*LDB*2)          // 18432
#define K3_SMEM  (2*K3_ATILE + 2*K3_BTILE)   // 106496

__global__ __launch_bounds__(256, 2) void k3_mma(const float* __restrict__ Wout) {
    extern __shared__ char smem[];
    const int n    = blockIdx.y;
    const int n0   = blockIdx.x * 64;
    const int ksp  = blockIdx.z;
    const int kbase = ksp * 2048;
    const int tid = threadIdx.x;
    const int lane = tid & 31, wid = tid >> 5;
    const int warp_m = (wid >> 1) * 32, warp_n = (wid & 1) * 32;
    const uint32_t sb = smem_u32(smem);
    const uint32_t sAhi = sb, sAlo = sb + K3_ATILE;
    const uint32_t sBhi = sb + 2*K3_ATILE, sBlo = sBhi + K3_BTILE;

    const __nv_bfloat16* Ah = g_pooled_hi + (size_t)n*BATCH*KDIM;
    const __nv_bfloat16* Al = g_pooled_lo + (size_t)n*BATCH*KDIM;
    const float* B = Wout + (size_t)n*KDIM*OUT;

    float acc[2][4][4];
    #pragma unroll
    for (int mi = 0; mi < 2; ++mi)
        #pragma unroll
        for (int nf = 0; nf < 4; ++nf)
            #pragma unroll
            for (int j = 0; j < 4; ++j) acc[mi][nf][j] = 0.f;

    const int cg = (tid & 15) * 4;
    const int kr = tid >> 4;
    const int arow = tid >> 4, ac8 = (tid & 15) * 8;

    float4 rB[8];
    #pragma unroll
    for (int i = 0; i < 8; ++i)
        rB[i] = *reinterpret_cast<const float4*>(B + (size_t)(kbase + kr + i*16)*OUT + n0 + cg);

    for (int kc = 0; kc < 16; ++kc) {
        // A chunk via cp.async (overlaps B convert below)
        #pragma unroll
        for (int i = 0; i < 8; ++i) {
            int row = arow + i*16;
            size_t gA = (size_t)row*KDIM + kbase + kc*128 + ac8;
            uint32_t so = (uint32_t)(row*LDA + ac8) * 2;
            cpa16(sAhi + so, Ah + gA);
            cpa16(sAlo + so, Al + gA);
        }
        CPA_COMMIT();
        // B convert+store from prefetched regs
        #pragma unroll
        for (int i = 0; i < 8; ++i) {
            float4 v = rB[i];
            __nv_bfloat16 h0 = __float2bfloat16(v.x), h1 = __float2bfloat16(v.y),
                          h2 = __float2bfloat16(v.z), h3 = __float2bfloat16(v.w);
            int o = ((kr + i*16)*LDB + cg) * 2;
            *reinterpret_cast<unsigned long long*>(smem + 2*K3_ATILE + o) =
                pack4bf(v.x, v.y, v.z, v.w);
            *reinterpret_cast<unsigned long long*>(smem + 2*K3_ATILE + K3_BTILE + o) =
                pack4bf(v.x - __bfloat162float(h0), v.y - __bfloat162float(h1),
                        v.z - __bfloat162float(h2), v.w - __bfloat162float(h3));
        }
        CPA_WAIT0();
        __syncthreads();
        // prefetch next B chunk (hidden under MMA)
        if (kc + 1 < 16) {
            #pragma unroll
            for (int i = 0; i < 8; ++i)
                rB[i] = *reinterpret_cast<const float4*>(
                    B + (size_t)(kbase + (kc+1)*128 + kr + i*16)*OUT + n0 + cg);
        }
        mma_tile<2,4>(sAhi, sAlo, sBhi, sBlo, lane, warp_m, warp_n, acc);
        __syncthreads();
    }

    // store fp32 partial
    float* pp = g_part + ((size_t)ksp*NBINS + n)*BATCH*OUT;
    const int g = lane >> 2, t2 = (lane & 3) * 2;
    #pragma unroll
    for (int mi = 0; mi < 2; ++mi) {
        #pragma unroll
        for (int nf = 0; nf < 4; ++nf) {
            int col = n0 + warp_n + nf*8 + t2;
            #pragma unroll
            for (int h = 0; h < 2; ++h) {
                int row = warp_m + mi*16 + g + h*8;
                *reinterpret_cast<float2*>(pp + (size_t)row*OUT + col) =
                    make_float2(acc[mi][nf][2*h], acc[mi][nf][2*h+1]);
            }
        }
    }
}

// K3 epilogue: feat = pmax + leaky(part0 + part1). Pure float4 stream.
__global__ __launch_bounds__(256) void k3e_epi() {
    int i4 = blockIdx.x * 256 + threadIdx.x;   // < 253952
    const float4* p0 = reinterpret_cast<const float4*>(g_part);
    const float4* p1 = reinterpret_cast<const float4*>(g_part + (size_t)NBINS*BATCH*OUT);
    const float4* pm = reinterpret_cast<const float4*>(g_pmax);
    float4 a = p0[i4], b = p1[i4], m = pm[i4];
    float4 o;
    float s;
    s = a.x + b.x; o.x = ((s >= 0.f) ? s : 0.01f*s) + m.x;
    s = a.y + b.y; o.y = ((s >= 0.f) ? s : 0.01f*s) + m.y;
    s = a.z + b.z; o.z = ((s >= 0.f) ? s : 0.01f*s) + m.z;
    s = a.w + b.w; o.w = ((s >= 0.f) ? s : 0.01f*s) + m.w;
    reinterpret_cast<float4*>(g_feat)[i4] = o;
}

// =====================================================================
// K4: outputs = feat @ FForward -> out1 [B, n, O]. FFMA2 (small).
// =====================================================================
__global__ __launch_bounds__(256, 2) void k4_ff(const float* __restrict__ FF, float* __restrict__ out1) {
    int n  = blockIdx.y;
    int n0 = blockIdx.x * 128;
    const float* A = g_feat + (size_t)n*BATCH*CH;
    const float* B = FF + (size_t)n*CH*OUT;

    __shared__ float As[2][8][128];
    __shared__ float Bs[2][8][128];

    int tid = threadIdx.x;
    int arow = tid >> 1, akc = (tid & 1) * 4;
    int brow = tid >> 5, bnc = (tid & 31) * 4;
    int m0 = (tid >> 4) * 8, nn0 = (tid & 15) * 8;

    uint64_t acc[8][4];
    #pragma unroll
    for (int i = 0; i < 8; ++i)
        #pragma unroll
        for (int j = 0; j < 4; ++j) acc[i][j] = 0ULL;

    const int NT = CH / 8;
    float4 rA, rB;
    rA = *reinterpret_cast<const float4*>(A + (size_t)arow*CH + akc);
    rB = *reinterpret_cast<const float4*>(B + (size_t)brow*OUT + n0 + bnc);
    As[0][akc+0][arow] = rA.x; As[0][akc+1][arow] = rA.y;
    As[0][akc+2][arow] = rA.z; As[0][akc+3][arow] = rA.w;
    *reinterpret_cast<float4*>(&Bs[0][brow][bnc]) = rB;
    __syncthreads();

    for (int t = 0; t < NT; ++t) {
        int cur = t & 1;
        if (t + 1 < NT) {
            int k0 = (t+1)*8;
            rA = *reinterpret_cast<const float4*>(A + (size_t)arow*CH + k0 + akc);
            rB = *reinterpret_cast<const float4*>(B + (size_t)(k0 + brow)*OUT + n0 + bnc);
        }
        #pragma unroll
        for (int kk = 0; kk < 8; ++kk) {
            float4 a0 = *reinterpret_cast<const float4*>(&As[cur][kk][m0]);
            float4 a1 = *reinterpret_cast<const float4*>(&As[cur][kk][m0+4]);
            const uint64_t* bp = reinterpret_cast<const uint64_t*>(&Bs[cur][kk][nn0]);
            uint64_t b0 = bp[0], b1 = bp[1], b2 = bp[2], b3 = bp[3];
            float av[8] = {a0.x,a0.y,a0.z,a0.w,a1.x,a1.y,a1.z,a1.w};
            #pragma unroll
            for (int i = 0; i < 8; ++i) {
                uint64_t ad = dup2(av[i]);
                FMA2(acc[i][0], ad, b0); FMA2(acc[i][1], ad, b1);
                FMA2(acc[i][2], ad, b2); FMA2(acc[i][3], ad, b3);
            }
        }
        if (t + 1 < NT) {
            int nxt = 1 - cur;
            As[nxt][akc+0][arow] = rA.x; As[nxt][akc+1][arow] = rA.y;
            As[nxt][akc+2][arow] = rA.z; As[nxt][akc+3][arow] = rA.w;
            *reinterpret_cast<float4*>(&Bs[nxt][brow][bnc]) = rB;
        }
        __syncthreads();
    }

    #pragma unroll
    for (int i = 0; i < 8; ++i) {
        int m = m0 + i;
        float v[8];
        #pragma unroll
        for (int j = 0; j < 4; ++j) unpack2(acc[i][j], v[2*j], v[2*j+1]);
        float* op = out1 + (size_t)m*(NBINS*OUT) + n*OUT + n0 + nn0;
        *reinterpret_cast<float4*>(op)     = make_float4(v[0],v[1],v[2],v[3]);
        *reinterpret_cast<float4*>(op + 4) = make_float4(v[4],v[5],v[6],v[7]);
    }
}

// =====================================================================
// K5: per-bin BatchNorm; outputs bn as bf16 hi/lo. grid (31,4) x 64.
// =====================================================================
__global__ __launch_bounds__(64) void k5_bn(const float* __restrict__ out1,
                                            const float* __restrict__ gamma,
                                            const float* __restrict__ beta) {
    int n = blockIdx.x;
    int o = blockIdx.y * 64 + threadIdx.x;
    const float* base = out1 + n*OUT + o;
    const int STR = NBINS*OUT;
    float s = 0.f;
    #pragma unroll 4
    for (int b = 0; b < BATCH; ++b) s += base[(size_t)b*STR];
    float mean = s * (1.f/BATCH);
    float v = 0.f;
    #pragma unroll 4
    for (int b = 0; b < BATCH; ++b) { float d = base[(size_t)b*STR] - mean; v += d*d; }
    v *= (1.f/BATCH);
    float istd = rsqrtf(v + 1e-5f);
    float g = gamma[n*OUT + o], be = beta[n*OUT + o];
    __nv_bfloat16* bh = g_bn_hi + (size_t)n*BATCH*OUT + o;
    __nv_bfloat16* bl = g_bn_lo + (size_t)n*BATCH*OUT + o;
    #pragma unroll 4
    for (int b = 0; b < BATCH; ++b) {
        float val = g * (base[(size_t)b*STR] - mean) * istd + be;
        __nv_bfloat16 h = __float2bfloat16(val);
        bh[(size_t)b*OUT] = h;
        bl[(size_t)b*OUT] = __float2bfloat16(val - __bfloat162float(h));
    }
}

__global__ __launch_bounds__(64) void k5b_rn() {
    int nb = blockIdx.x;
    int tid = threadIdx.x;
    const __nv_bfloat16* rh = g_bn_hi + (size_t)nb*OUT;
    const __nv_bfloat16* rl = g_bn_lo + (size_t)nb*OUT;
    float s = 0.f;
    for (int i = tid; i < OUT; i += 64) {
        float v = __bfloat162float(rh[i]) + __bfloat162float(rl[i]);
        s += v*v;
    }
    #pragma unroll
    for (int o = 16; o > 0; o >>= 1) s += __shfl_xor_sync(0xffffffffu, s, o);
    __shared__ float ws[2];
    if ((tid & 31) == 0) ws[tid >> 5] = s;
    __syncthreads();
    if (tid == 0) g_invrn[nb] = 1.f / fmaxf(sqrtf(ws[0] + ws[1]), 1e-12f);
}

// =====================================================================
// K6 (HMMA bf16x3, pipelined): logits = (bn @ fc1d) * invrow * invcol
// 128x64 tiles, grid (157, 31), occ 2. cp.async A + reg-prefetch B.
// =====================================================================
#define K6_ATILE (128*LDA*2)          // 34816
#define K6_BTILE (128*LDB*2)          // 18432
#define K6_CSQ   (2*K6_ATILE + 2*K6_BTILE)   // 106496
#define K6_INV   (K6_CSQ + 16*64*4)          // 110592
#define K6_SMEM  (K6_INV + 64*4)             // 110848

__global__ __launch_bounds__(256, 2) void k6_mma(const float* __restrict__ fc,
                                                 float* __restrict__ out2) {
    extern __shared__ char smem[];
    const int n  = blockIdx.y;
    const int n0 = blockIdx.x * 64;
    const int tid = threadIdx.x;
    const int lane = tid & 31, wid = tid >> 5;
    const int warp_m = (wid >> 1) * 32, warp_n = (wid & 1) * 32;
    const uint32_t sb = smem_u32(smem);
    const uint32_t sAhi = sb, sAlo = sb + K6_ATILE;
    const uint32_t sBhi = sb + 2*K6_ATILE, sBlo = sBhi + K6_BTILE;

    const __nv_bfloat16* Ah = g_bn_hi + (size_t)n*BATCH*OUT;
    const __nv_bfloat16* Al = g_bn_lo + (size_t)n*BATCH*OUT;
    const float* Bg = fc + (size_t)n*OUT*NCLS;

    float acc[2][4][4];
    #pragma unroll
    for (int mi = 0; mi < 2; ++mi)
        #pragma unroll
        for (int nf = 0; nf < 4; ++nf)
            #pragma unroll
            for (int j = 0; j < 4; ++j) acc[mi][nf][j] = 0.f;

    const int cg = (tid & 15) * 4;
    const int kr = tid >> 4;
    const int arow = tid >> 4, ac8 = (tid & 15) * 8;
    const bool valid = (n0 + cg) < NCLS;
    float sq0 = 0.f, sq1 = 0.f, sq2 = 0.f, sq3 = 0.f;

    float4 rB[8];
    #pragma unroll
    for (int i = 0; i < 8; ++i)
        rB[i] = valid ? *reinterpret_cast<const float4*>(
                            Bg + (size_t)(kr + i*16)*NCLS + n0 + cg)
                      : make_float4(0.f, 0.f, 0.f, 0.f);

    for (int kc = 0; kc < 2; ++kc) {
        // A chunk via cp.async
        #pragma unroll
        for (int i = 0; i < 8; ++i) {
            int row = arow + i*16;
            size_t gA = (size_t)row*OUT + kc*128 + ac8;
            uint32_t so = (uint32_t)(row*LDA + ac8) * 2;
            cpa16(sAhi + so, Ah + gA);
            cpa16(sAlo + so, Al + gA);
        }
        CPA_COMMIT();
        // B convert+store + sumsq from prefetched regs
        #pragma unroll
        for (int i = 0; i < 8; ++i) {
            float4 v = rB[i];
            sq0 += v.x*v.x; sq1 += v.y*v.y; sq2 += v.z*v.z; sq3 += v.w*v.w;
            __nv_bfloat16 h0 = __float2bfloat16(v.x), h1 = __float2bfloat16(v.y),
                          h2 = __float2bfloat16(v.z), h3 = __float2bfloat16(v.w);
            int o = ((kr + i*16)*LDB + cg) * 2;
            *reinterpret_cast<unsigned long long*>(smem + 2*K6_ATILE + o) =
                pack4bf(v.x, v.y, v.z, v.w);
            *reinterpret_cast<unsigned long long*>(smem + 2*K6_ATILE + K6_BTILE + o) =
                pack4bf(v.x - __bfloat162float(h0), v.y - __bfloat162float(h1),
                        v.z - __bfloat162float(h2), v.w - __bfloat162float(h3));
        }
        CPA_WAIT0();
        __syncthreads();
        if (kc == 0) {
            #pragma unroll
            for (int i = 0; i < 8; ++i)
                rB[i] = valid ? *reinterpret_cast<const float4*>(
                                    Bg + (size_t)(128 + kr + i*16)*NCLS + n0 + cg)
                              : make_float4(0.f, 0.f, 0.f, 0.f);
        }
        mma_tile<2,4>(sAhi, sAlo, sBhi, sBlo, lane, warp_m, warp_n, acc);
        __syncthreads();
    }

    // column inv-norms
    float* csq = reinterpret_cast<float*>(smem + K6_CSQ);
    *reinterpret_cast<float4*>(csq + kr*64 + cg) = make_float4(sq0, sq1, sq2, sq3);
    __syncthreads();
    float* inv = reinterpret_cast<float*>(smem + K6_INV);
    if (tid < 64) {
        float ss = 0.f;
        #pragma unroll
        for (int r = 0; r < 16; ++r) ss += csq[r*64 + tid];
        inv[tid] = 1.f / fmaxf(sqrtf(ss), 1e-12f);
    }
    __syncthreads();

    // epilogue
    const int g = lane >> 2, t2 = (lane & 3) * 2;
    #pragma unroll
    for (int mi = 0; mi < 2; ++mi) {
        #pragma unroll
        for (int nf = 0; nf < 4; ++nf) {
            int col = warp_n + nf*8 + t2;
            if (n0 + col >= NCLS) continue;
            float ic0 = inv[col], ic1 = inv[col+1];
            #pragma unroll
            for (int h = 0; h < 2; ++h) {
                int row = warp_m + mi*16 + g + h*8;
                float ir = g_invrn[n*BATCH + row];
                *reinterpret_cast<float2*>(
                    out2 + (size_t)row*(NBINS*NCLS) + n*NCLS + n0 + col) =
                    make_float2(acc[mi][nf][2*h]*ir*ic0, acc[mi][nf][2*h+1]*ir*ic1);
            }
        }
    }
}

// =====================================================================
extern "C" void kernel_launch(void* const* d_in, const int* in_sizes, int n_in,
                              void* d_out, int out_size) {
    const float* x     = (const float*)d_in[0];
    const float* Wmask = (const float*)d_in[1];
    const float* Wout  = (const float*)d_in[2];
    const float* FF    = (const float*)d_in[3];
    const float* gamma = (const float*)d_in[4];
    const float* beta  = (const float*)d_in[5];
    const float* fc1d  = (const float*)d_in[6];
    float* out  = (float*)d_out;
    float* out1 = out;                                   // [128,31,256]
    float* out2 = out + (size_t)BATCH*NBINS*OUT;         // [128,31,10000]

    cudaFuncSetAttribute(k3_mma, cudaFuncAttributeMaxDynamicSharedMemorySize, K3_SMEM);
    cudaFuncSetAttribute(k6_mma, cudaFuncAttributeMaxDynamicSharedMemorySize, K6_SMEM);

    k1_hmap<<<BATCH*TT*8, 512>>>(x);
    k2_mask<<<NB, 512>>>(Wmask);
    k3_mma<<<dim3(4, NBINS, 2), 256, K3_SMEM>>>(Wout);
    k3e_epi<<<992, 256>>>();
    k4_ff<<<dim3(2, NBINS), 256>>>(FF, out1);
    k5_bn<<<dim3(NBINS, 4), 64>>>(out1, gamma, beta);
    k5b_rn<<<NB, 64>>>();
    k6_mma<<<dim3((NCLS + 63) / 64, NBINS), 256, K6_SMEM>>>(fc1d, out2);
}

// round 7
// speedup vs baseline: 1.7920x; 1.1667x over previous
#include <cuda_runtime.h>
#include <cuda_fp16.h>
#include <cstdint>

// ---------------- problem constants ----------------
#define BATCH 128
#define CH    256
#define TT    30
#define WW    11
#define HW    176
#define NBINS 31
#define RED   16
#define KDIM  4096
#define OUT   256
#define NCLS  10000
#define NB    (NBINS*BATCH)

#define LDA   136   // A smem row stride (fp16)
#define LDB   72    // B smem row stride (fp16)

// ---------------- scratch ----------------
__device__ float g_p[(size_t)NBINS*BATCH*TT*CH];
__device__ float g_pmax[NBINS*BATCH*CH];
__device__ __half g_pooled_hi[(size_t)NBINS*BATCH*KDIM];
__device__ __half g_pooled_lo[(size_t)NBINS*BATCH*KDIM];
__device__ __half g_feat_hi[NBINS*BATCH*CH];
__device__ __half g_feat_lo[NBINS*BATCH*CH];
__device__ __half g_bn_hi[NBINS*BATCH*OUT];
__device__ __half g_bn_lo[NBINS*BATCH*OUT];
__device__ float g_invrn[NB];
__device__ float g_rowsq[8][NB];
__device__ float g_part[(size_t)2*NBINS*BATCH*OUT];

// ---------------- helpers ----------------
__device__ __forceinline__ uint32_t smem_u32(const void* p) {
    uint32_t a;
    asm("{ .reg .u64 t; cvta.to.shared.u64 t, %1; cvt.u32.u64 %0, t; }" : "=r"(a) : "l"(p));
    return a;
}
__device__ __forceinline__ void cpa16(uint32_t dst, const void* src) {
    asm volatile("cp.async.cg.shared.global [%0], [%1], 16;" :: "r"(dst), "l"(src));
}
#define CPA_COMMIT() asm volatile("cp.async.commit_group;" ::: "memory")
#define CPA_WAIT0()  asm volatile("cp.async.wait_group 0;" ::: "memory")

__device__ __forceinline__ void ldsm4(uint32_t a[4], uint32_t addr) {
    asm volatile("ldmatrix.sync.aligned.m8n8.x4.shared.b16 {%0,%1,%2,%3}, [%4];"
        : "=r"(a[0]),"=r"(a[1]),"=r"(a[2]),"=r"(a[3]) : "r"(addr));
}
__device__ __forceinline__ void ldsm4t(uint32_t a[4], uint32_t addr) {
    asm volatile("ldmatrix.sync.aligned.m8n8.x4.trans.shared.b16 {%0,%1,%2,%3}, [%4];"
        : "=r"(a[0]),"=r"(a[1]),"=r"(a[2]),"=r"(a[3]) : "r"(addr));
}
__device__ __forceinline__ void mma_f16(float d[4], const uint32_t a[4], uint32_t b0, uint32_t b1) {
    asm volatile("mma.sync.aligned.m16n8k16.row.col.f32.f16.f16.f32 "
        "{%0,%1,%2,%3}, {%4,%5,%6,%7}, {%8,%9}, {%0,%1,%2,%3};"
        : "+f"(d[0]),"+f"(d[1]),"+f"(d[2]),"+f"(d[3])
        : "r"(a[0]),"r"(a[1]),"r"(a[2]),"r"(a[3]), "r"(b0),"r"(b1));
}
__device__ __forceinline__ unsigned pack2h(float a, float b) {
    __half2 h = __floats2half2_rn(a, b);
    return *reinterpret_cast<unsigned*>(&h);
}
__device__ __forceinline__ unsigned long long pack4h(float a, float b, float c, float d) {
    return ((unsigned long long)pack2h(c, d) << 32) | pack2h(a, b);
}
__device__ __forceinline__ float h_lo(float v) {
    return v - __half2float(__float2half_rn(v));
}

// fp16x2 tile step over one K=128 chunk: acc += Ahi*B + Alo*B.
// A smem [m][k] stride LDA (hi & lo); B smem [k][n] stride LDB (single).
template<int MI, int NF>
__device__ __forceinline__ void mma_tile2(uint32_t sAhi, uint32_t sAlo, uint32_t sB,
                                          int lane, int warp_m, int warp_n,
                                          float (&acc)[MI][NF][4]) {
    const int l15 = lane & 15;
    const int l16 = (lane >> 4) << 3;
    #pragma unroll
    for (int ks = 0; ks < 8; ++ks) {
        const int k = ks * 16;
        uint32_t ahi[MI][4], alo[MI][4], bb[NF][2];
        #pragma unroll
        for (int mi = 0; mi < MI; ++mi) {
            uint32_t ao = ((warp_m + mi*16 + l15)*LDA + k + l16) * 2;
            ldsm4(ahi[mi], sAhi + ao);
            ldsm4(alo[mi], sAlo + ao);
        }
        #pragma unroll
        for (int q = 0; q < NF/2; ++q) {
            uint32_t bo = ((k + l15)*LDB + warp_n + q*16 + l16) * 2;
            uint32_t r[4];
            ldsm4t(r, sB + bo);
            bb[2*q][0] = r[0]; bb[2*q][1] = r[1];
            bb[2*q+1][0] = r[2]; bb[2*q+1][1] = r[3];
        }
        #pragma unroll
        for (int mi = 0; mi < MI; ++mi) {
            #pragma unroll
            for (int nf = 0; nf < NF; ++nf) {
                mma_f16(acc[mi][nf], ahi[mi], bb[nf][0], bb[nf][1]);
                mma_f16(acc[mi][nf], alo[mi], bb[nf][0], bb[nf][1]);
            }
        }
    }
}

// =====================================================================
// K1: horizontal strip pooling.
// =====================================================================
__global__ __launch_bounds__(512) void k1_hmap(const float* __restrict__ x) {
    int bid = blockIdx.x;
    int cg = bid & 7;
    int t  = (bid >> 3) % TT;
    int b  = bid / (TT * 8);

    __shared__ float xs[32][180];
    __shared__ float rsum[32][16];
    __shared__ float rmax[32][16];

    const float* xb = x + (((size_t)b*CH + cg*32)*TT + t) * HW;
    int tid = threadIdx.x;

    for (int idx = tid; idx < 32*44; idx += 512) {
        int c = idx / 44, e = idx % 44;
        float4 v = *reinterpret_cast<const float4*>(xb + (size_t)c*TT*HW + e*4);
        *reinterpret_cast<float4*>(&xs[c][e*4]) = v;
    }
    __syncthreads();
    {
        int c = tid >> 4, h = tid & 15;
        float s = 0.f, m = -1e30f;
        #pragma unroll
        for (int w = 0; w < WW; ++w) {
            float v = xs[c][h*WW + w];
            s += v; m = fmaxf(m, v);
        }
        rsum[c][h] = s; rmax[c][h] = m;
    }
    __syncthreads();

    for (int oi = tid; oi < NBINS*32; oi += 512) {
        int n = oi >> 5;
        int c = oi & 31;
        int start, len;
        if      (n == 0) { start = 0;          len = 16; }
        else if (n < 3)  { start = (n-1)*8;    len = 8;  }
        else if (n < 7)  { start = (n-3)*4;    len = 4;  }
        else if (n < 15) { start = (n-7)*2;    len = 2;  }
        else             { start = n-15;       len = 1;  }
        float s = 0.f, m = -1e30f;
        for (int h = 0; h < len; ++h) {
            s += rsum[c][start+h];
            m = fmaxf(m, rmax[c][start+h]);
        }
        g_p[(((size_t)n*BATCH + b)*TT + t)*CH + cg*32 + c] = s / (float)(len*WW) + m;
    }
}

// =====================================================================
// K2: mask logits + softmax + attention pooling + pmax.
// Pooled stored as fp16 hi/lo.
// =====================================================================
__global__ __launch_bounds__(512) void k2_mask(const float* __restrict__ Wmask) {
    int nb = blockIdx.x;
    int n = nb >> 7;
    int b = nb & 127;
    __shared__ float ps[TT][CH];
    __shared__ float wms[CH][RED];
    __shared__ float lg[TT][RED];

    int tid = threadIdx.x;
    const float* pg = g_p + ((size_t)n*BATCH + b)*TT*CH;
    for (int i = tid; i < TT*CH/4; i += 512) {
        float4 v = *reinterpret_cast<const float4*>(pg + i*4);
        *reinterpret_cast<float4*>(&ps[0][0] + i*4) = v;
    }
    const float* wg = Wmask + (size_t)n*CH*RED;
    for (int i = tid; i < CH*RED/4; i += 512) {
        float4 v = *reinterpret_cast<const float4*>(wg + i*4);
        *reinterpret_cast<float4*>(&wms[0][0] + i*4) = v;
    }
    __syncthreads();

    if (tid < TT*RED) {
        int t = tid >> 4, r = tid & 15;
        float acc = 0.f;
        #pragma unroll 8
        for (int c = 0; c < CH; ++c) acc += ps[t][c] * wms[c][r];
        lg[t][r] = acc;
    }
    __syncthreads();

    if (tid < RED) {
        int r = tid;
        float m = -1e30f;
        for (int t = 0; t < TT; ++t) m = fmaxf(m, lg[t][r]);
        float s = 0.f;
        for (int t = 0; t < TT; ++t) { float e = expf(lg[t][r] - m); lg[t][r] = e; s += e; }
        float inv = 1.f / s;
        for (int t = 0; t < TT; ++t) lg[t][r] *= inv;
    }
    __syncthreads();

    {
        int c = tid & 255;
        int rh = tid >> 8;
        float acc[8];
        #pragma unroll
        for (int r = 0; r < 8; ++r) acc[r] = 0.f;
        float pm = -1e30f;
        for (int t = 0; t < TT; ++t) {
            float pv = ps[t][c];
            pm = fmaxf(pm, pv);
            float4 m0 = *reinterpret_cast<const float4*>(&lg[t][rh*8]);
            float4 m1 = *reinterpret_cast<const float4*>(&lg[t][rh*8+4]);
            acc[0] += pv*m0.x; acc[1] += pv*m0.y; acc[2] += pv*m0.z; acc[3] += pv*m0.w;
            acc[4] += pv*m1.x; acc[5] += pv*m1.y; acc[6] += pv*m1.z; acc[7] += pv*m1.w;
        }
        size_t base = ((size_t)n*BATCH + b)*KDIM + c*RED + rh*8;
        float lo[8];
        #pragma unroll
        for (int r = 0; r < 8; ++r) lo[r] = h_lo(acc[r]);
        unsigned long long* dh = reinterpret_cast<unsigned long long*>(g_pooled_hi + base);
        unsigned long long* dl = reinterpret_cast<unsigned long long*>(g_pooled_lo + base);
        dh[0] = pack4h(acc[0],acc[1],acc[2],acc[3]); dh[1] = pack4h(acc[4],acc[5],acc[6],acc[7]);
        dl[0] = pack4h(lo[0],lo[1],lo[2],lo[3]);     dl[1] = pack4h(lo[4],lo[5],lo[6],lo[7]);
        if (rh == 0) g_pmax[((size_t)n*BATCH + b)*CH + c] = pm;
    }
}

// =====================================================================
// K3 (fp16x2, split-K=2, pipelined): partial = pooled @ Wout
// BM=128, BN=64. grid (4 N, NBINS, 2 Ksplit) = 248 CTAs, occ 2.
// =====================================================================
#define K3_ATILE (128*LDA*2)          // 34816
#define K3_BTILE (128*LDB*2)          // 18432
#define K3_SMEM  (2*K3_ATILE + K3_BTILE)     // 88064

__global__ __launch_bounds__(256, 2) void k3_mma(const float* __restrict__ Wout) {
    extern __shared__ char smem[];
    const int n    = blockIdx.y;
    const int n0   = blockIdx.x * 64;
    const int ksp  = blockIdx.z;
    const int kbase = ksp * 2048;
    const int tid = threadIdx.x;
    const int lane = tid & 31, wid = tid >> 5;
    const int warp_m = (wid >> 1) * 32, warp_n = (wid & 1) * 32;
    const uint32_t sb = smem_u32(smem);
    const uint32_t sAhi = sb, sAlo = sb + K3_ATILE, sB = sb + 2*K3_ATILE;

    const __half* Ah = g_pooled_hi + (size_t)n*BATCH*KDIM;
    const __half* Al = g_pooled_lo + (size_t)n*BATCH*KDIM;
    const float* B = Wout + (size_t)n*KDIM*OUT;

    float acc[2][4][4];
    #pragma unroll
    for (int mi = 0; mi < 2; ++mi)
        #pragma unroll
        for (int nf = 0; nf < 4; ++nf)
            #pragma unroll
            for (int j = 0; j < 4; ++j) acc[mi][nf][j] = 0.f;

    const int cg = (tid & 15) * 4;
    const int kr = tid >> 4;
    const int arow = tid >> 4, ac8 = (tid & 15) * 8;

    float4 rB[8];
    #pragma unroll
    for (int i = 0; i < 8; ++i)
        rB[i] = *reinterpret_cast<const float4*>(B + (size_t)(kbase + kr + i*16)*OUT + n0 + cg);

    for (int kc = 0; kc < 16; ++kc) {
        #pragma unroll
        for (int i = 0; i < 8; ++i) {
            int row = arow + i*16;
            size_t gA = (size_t)row*KDIM + kbase + kc*128 + ac8;
            uint32_t so = (uint32_t)(row*LDA + ac8) * 2;
            cpa16(sAhi + so, Ah + gA);
            cpa16(sAlo + so, Al + gA);
        }
        CPA_COMMIT();
        #pragma unroll
        for (int i = 0; i < 8; ++i) {
            float4 v = rB[i];
            int o = ((kr + i*16)*LDB + cg) * 2;
            *reinterpret_cast<unsigned long long*>(smem + 2*K3_ATILE + o) =
                pack4h(v.x, v.y, v.z, v.w);
        }
        CPA_WAIT0();
        __syncthreads();
        if (kc + 1 < 16) {
            #pragma unroll
            for (int i = 0; i < 8; ++i)
                rB[i] = *reinterpret_cast<const float4*>(
                    B + (size_t)(kbase + (kc+1)*128 + kr + i*16)*OUT + n0 + cg);
        }
        mma_tile2<2,4>(sAhi, sAlo, sB, lane, warp_m, warp_n, acc);
        __syncthreads();
    }

    float* pp = g_part + ((size_t)ksp*NBINS + n)*BATCH*OUT;
    const int g = lane >> 2, t2 = (lane & 3) * 2;
    #pragma unroll
    for (int mi = 0; mi < 2; ++mi) {
        #pragma unroll
        for (int nf = 0; nf < 4; ++nf) {
            int col = n0 + warp_n + nf*8 + t2;
            #pragma unroll
            for (int h = 0; h < 2; ++h) {
                int row = warp_m + mi*16 + g + h*8;
                *reinterpret_cast<float2*>(pp + (size_t)row*OUT + col) =
                    make_float2(acc[mi][nf][2*h], acc[mi][nf][2*h+1]);
            }
        }
    }
}

// K3 epilogue: feat = pmax + leaky(part0+part1) -> fp16 hi/lo.
__global__ __launch_bounds__(256) void k3e_epi() {
    int i4 = blockIdx.x * 256 + threadIdx.x;   // < 253952
    const float4* p0 = reinterpret_cast<const float4*>(g_part);
    const float4* p1 = reinterpret_cast<const float4*>(g_part + (size_t)NBINS*BATCH*OUT);
    const float4* pm = reinterpret_cast<const float4*>(g_pmax);
    float4 a = p0[i4], b = p1[i4], m = pm[i4];
    float o[4];
    float s;
    s = a.x + b.x; o[0] = ((s >= 0.f) ? s : 0.01f*s) + m.x;
    s = a.y + b.y; o[1] = ((s >= 0.f) ? s : 0.01f*s) + m.y;
    s = a.z + b.z; o[2] = ((s >= 0.f) ? s : 0.01f*s) + m.z;
    s = a.w + b.w; o[3] = ((s >= 0.f) ? s : 0.01f*s) + m.w;
    reinterpret_cast<unsigned long long*>(g_feat_hi)[i4] = pack4h(o[0], o[1], o[2], o[3]);
    reinterpret_cast<unsigned long long*>(g_feat_lo)[i4] =
        pack4h(h_lo(o[0]), h_lo(o[1]), h_lo(o[2]), h_lo(o[3]));
}

// =====================================================================
// K4 (fp16x2 + fused BatchNorm): outputs = feat @ FForward.
// BM=128 (full batch), BN=64, K=256. grid (4, NBINS), occ 2.
// Epilogue: per-column batch stats in-CTA -> out1 fp32, bn fp16 hi/lo,
// row-sumsq partials (8 slots).
// =====================================================================
#define K4_SMEM  (2*K3_ATILE + K3_BTILE)     // 88064; obuf reuse = 33.8KB

__global__ __launch_bounds__(256, 2) void k4_ff(const float* __restrict__ FF,
                                                const float* __restrict__ gamma,
                                                const float* __restrict__ beta,
                                                float* __restrict__ out1) {
    extern __shared__ char smem[];
    const int n  = blockIdx.y;
    const int n0 = blockIdx.x * 64;
    const int tid = threadIdx.x;
    const int lane = tid & 31, wid = tid >> 5;
    const int warp_m = (wid >> 1) * 32, warp_n = (wid & 1) * 32;
    const uint32_t sb = smem_u32(smem);
    const uint32_t sAhi = sb, sAlo = sb + K3_ATILE, sB = sb + 2*K3_ATILE;

    const __half* Ah = g_feat_hi + (size_t)n*BATCH*CH;
    const __half* Al = g_feat_lo + (size_t)n*BATCH*CH;
    const float* B = FF + (size_t)n*CH*OUT;

    float acc[2][4][4];
    #pragma unroll
    for (int mi = 0; mi < 2; ++mi)
        #pragma unroll
        for (int nf = 0; nf < 4; ++nf)
            #pragma unroll
            for (int j = 0; j < 4; ++j) acc[mi][nf][j] = 0.f;

    const int cg = (tid & 15) * 4;
    const int kr = tid >> 4;
    const int arow = tid >> 4, ac8 = (tid & 15) * 8;

    float4 rB[8];
    #pragma unroll
    for (int i = 0; i < 8; ++i)
        rB[i] = *reinterpret_cast<const float4*>(B + (size_t)(kr + i*16)*OUT + n0 + cg);

    for (int kc = 0; kc < 2; ++kc) {
        #pragma unroll
        for (int i = 0; i < 8; ++i) {
            int row = arow + i*16;
            size_t gA = (size_t)row*CH + kc*128 + ac8;
            uint32_t so = (uint32_t)(row*LDA + ac8) * 2;
            cpa16(sAhi + so, Ah + gA);
            cpa16(sAlo + so, Al + gA);
        }
        CPA_COMMIT();
        #pragma unroll
        for (int i = 0; i < 8; ++i) {
            float4 v = rB[i];
            int o = ((kr + i*16)*LDB + cg) * 2;
            *reinterpret_cast<unsigned long long*>(smem + 2*K3_ATILE + o) =
                pack4h(v.x, v.y, v.z, v.w);
        }
        CPA_WAIT0();
        __syncthreads();
        if (kc == 0) {
            #pragma unroll
            for (int i = 0; i < 8; ++i)
                rB[i] = *reinterpret_cast<const float4*>(
                    B + (size_t)(128 + kr + i*16)*OUT + n0 + cg);
        }
        mma_tile2<2,4>(sAhi, sAlo, sB, lane, warp_m, warp_n, acc);
        __syncthreads();
    }

    // ---- fused BatchNorm epilogue ----
    float* ob = reinterpret_cast<float*>(smem);        // [128][65]
    float* smean = ob + 128*65;
    float* sistd = smean + 64;
    const int g = lane >> 2, t2 = (lane & 3) * 2;

    #pragma unroll
    for (int mi = 0; mi < 2; ++mi)
        #pragma unroll
        for (int nf = 0; nf < 4; ++nf) {
            int col = warp_n + nf*8 + t2;
            #pragma unroll
            for (int h = 0; h < 2; ++h) {
                int row = warp_m + mi*16 + g + h*8;
                ob[row*65 + col]     = acc[mi][nf][2*h];
                ob[row*65 + col + 1] = acc[mi][nf][2*h+1];
            }
        }
    __syncthreads();

    if (tid < 64) {
        float s = 0.f;
        #pragma unroll 8
        for (int r = 0; r < 128; ++r) s += ob[r*65 + tid];
        float mean = s * (1.f/128.f);
        float v = 0.f;
        #pragma unroll 8
        for (int r = 0; r < 128; ++r) { float d = ob[r*65 + tid] - mean; v += d*d; }
        smean[tid] = mean;
        sistd[tid] = rsqrtf(v * (1.f/128.f) + 1e-5f);
    }
    __syncthreads();

    const int slot = blockIdx.x * 2 + (wid & 1);
    #pragma unroll
    for (int mi = 0; mi < 2; ++mi) {
        #pragma unroll
        for (int h = 0; h < 2; ++h) {
            int row = warp_m + mi*16 + g + h*8;
            float rsq = 0.f;
            #pragma unroll
            for (int nf = 0; nf < 4; ++nf) {
                int col = warp_n + nf*8 + t2;
                float o0 = acc[mi][nf][2*h], o1 = acc[mi][nf][2*h+1];
                // outputs (fp32) -> out1 [B, n, O]
                *reinterpret_cast<float2*>(
                    out1 + (size_t)row*(NBINS*OUT) + n*OUT + n0 + col) = make_float2(o0, o1);
                // bn
                float b0 = gamma[n*OUT + n0 + col]   * (o0 - smean[col])   * sistd[col]   + beta[n*OUT + n0 + col];
                float b1 = gamma[n*OUT + n0 + col+1] * (o1 - smean[col+1]) * sistd[col+1] + beta[n*OUT + n0 + col+1];
                size_t bo = (size_t)n*BATCH*OUT + (size_t)row*OUT + n0 + col;
                *reinterpret_cast<unsigned*>(g_bn_hi + bo) = pack2h(b0, b1);
                *reinterpret_cast<unsigned*>(g_bn_lo + bo) = pack2h(h_lo(b0), h_lo(b1));
                rsq += b0*b0 + b1*b1;
            }
            rsq += __shfl_xor_sync(0xffffffffu, rsq, 1);
            rsq += __shfl_xor_sync(0xffffffffu, rsq, 2);
            if ((lane & 3) == 0) g_rowsq[slot][n*BATCH + row] = rsq;
        }
    }
}

// K5c: inverse row norms from 8 partials.
__global__ __launch_bounds__(256) void k5c_rn() {
    int idx = blockIdx.x * 256 + threadIdx.x;
    if (idx < NB) {
        float s = 0.f;
        #pragma unroll
        for (int j = 0; j < 8; ++j) s += g_rowsq[j][idx];
        g_invrn[idx] = 1.f / fmaxf(sqrtf(s), 1e-12f);
    }
}

// =====================================================================
// K6 (fp16x2, pipelined): logits = (bn @ fc1d) * invrow * invcol
// 128x64 tiles, grid (157, 31), occ 2. cp.async A + reg-prefetch B.
// =====================================================================
#define K6_CSQ   (2*K3_ATILE + K3_BTILE)     // 88064
#define K6_INV   (K6_CSQ + 16*64*4)          // 92160
#define K6_SMEM  (K6_INV + 64*4)             // 92416

__global__ __launch_bounds__(256, 2) void k6_mma(const float* __restrict__ fc,
                                                 float* __restrict__ out2) {
    extern __shared__ char smem[];
    const int n  = blockIdx.y;
    const int n0 = blockIdx.x * 64;
    const int tid = threadIdx.x;
    const int lane = tid & 31, wid = tid >> 5;
    const int warp_m = (wid >> 1) * 32, warp_n = (wid & 1) * 32;
    const uint32_t sb = smem_u32(smem);
    const uint32_t sAhi = sb, sAlo = sb + K3_ATILE, sB = sb + 2*K3_ATILE;

    const __half* Ah = g_bn_hi + (size_t)n*BATCH*OUT;
    const __half* Al = g_bn_lo + (size_t)n*BATCH*OUT;
    const float* Bg = fc + (size_t)n*OUT*NCLS;

    float acc[2][4][4];
    #pragma unroll
    for (int mi = 0; mi < 2; ++mi)
        #pragma unroll
        for (int nf = 0; nf < 4; ++nf)
            #pragma unroll
            for (int j = 0; j < 4; ++j) acc[mi][nf][j] = 0.f;

    const int cg = (tid & 15) * 4;
    const int kr = tid >> 4;
    const int arow = tid >> 4, ac8 = (tid & 15) * 8;
    const bool valid = (n0 + cg) < NCLS;
    float sq0 = 0.f, sq1 = 0.f, sq2 = 0.f, sq3 = 0.f;

    float4 rB[8];
    #pragma unroll
    for (int i = 0; i < 8; ++i)
        rB[i] = valid ? *reinterpret_cast<const float4*>(
                            Bg + (size_t)(kr + i*16)*NCLS + n0 + cg)
                      : make_float4(0.f, 0.f, 0.f, 0.f);

    for (int kc = 0; kc < 2; ++kc) {
        #pragma unroll
        for (int i = 0; i < 8; ++i) {
            int row = arow + i*16;
            size_t gA = (size_t)row*OUT + kc*128 + ac8;
            uint32_t so = (uint32_t)(row*LDA + ac8) * 2;
            cpa16(sAhi + so, Ah + gA);
            cpa16(sAlo + so, Al + gA);
        }
        CPA_COMMIT();
        #pragma unroll
        for (int i = 0; i < 8; ++i) {
            float4 v = rB[i];
            sq0 += v.x*v.x; sq1 += v.y*v.y; sq2 += v.z*v.z; sq3 += v.w*v.w;
            int o = ((kr + i*16)*LDB + cg) * 2;
            *reinterpret_cast<unsigned long long*>(smem + 2*K3_ATILE + o) =
                pack4h(v.x, v.y, v.z, v.w);
        }
        CPA_WAIT0();
        __syncthreads();
        if (kc == 0) {
            #pragma unroll
            for (int i = 0; i < 8; ++i)
                rB[i] = valid ? *reinterpret_cast<const float4*>(
                                    Bg + (size_t)(128 + kr + i*16)*NCLS + n0 + cg)
                              : make_float4(0.f, 0.f, 0.f, 0.f);
        }
        mma_tile2<2,4>(sAhi, sAlo, sB, lane, warp_m, warp_n, acc);
        __syncthreads();
    }

    // column inv-norms
    float* csq = reinterpret_cast<float*>(smem + K6_CSQ);
    *reinterpret_cast<float4*>(csq + kr*64 + cg) = make_float4(sq0, sq1, sq2, sq3);
    __syncthreads();
    float* inv = reinterpret_cast<float*>(smem + K6_INV);
    if (tid < 64) {
        float ss = 0.f;
        #pragma unroll
        for (int r = 0; r < 16; ++r) ss += csq[r*64 + tid];
        inv[tid] = 1.f / fmaxf(sqrtf(ss), 1e-12f);
    }
    __syncthreads();

    const int g = lane >> 2, t2 = (lane & 3) * 2;
    #pragma unroll
    for (int mi = 0; mi < 2; ++mi) {
        #pragma unroll
        for (int nf = 0; nf < 4; ++nf) {
            int col = warp_n + nf*8 + t2;
            if (n0 + col >= NCLS) continue;
            float ic0 = inv[col], ic1 = inv[col+1];
            #pragma unroll
            for (int h = 0; h < 2; ++h) {
                int row = warp_m + mi*16 + g + h*8;
                float ir = g_invrn[n*BATCH + row];
                *reinterpret_cast<float2*>(
                    out2 + (size_t)row*(NBINS*NCLS) + n*NCLS + n0 + col) =
                    make_float2(acc[mi][nf][2*h]*ir*ic0, acc[mi][nf][2*h+1]*ir*ic1);
            }
        }
    }
}

// =====================================================================
extern "C" void kernel_launch(void* const* d_in, const int* in_sizes, int n_in,
                              void* d_out, int out_size) {
    const float* x     = (const float*)d_in[0];
    const float* Wmask = (const float*)d_in[1];
    const float* Wout  = (const float*)d_in[2];
    const float* FF    = (const float*)d_in[3];
    const float* gamma = (const float*)d_in[4];
    const float* beta  = (const float*)d_in[5];
    const float* fc1d  = (const float*)d_in[6];
    float* out  = (float*)d_out;
    float* out1 = out;                                   // [128,31,256]
    float* out2 = out + (size_t)BATCH*NBINS*OUT;         // [128,31,10000]

    cudaFuncSetAttribute(k3_mma, cudaFuncAttributeMaxDynamicSharedMemorySize, K3_SMEM);
    cudaFuncSetAttribute(k4_ff,  cudaFuncAttributeMaxDynamicSharedMemorySize, K4_SMEM);
    cudaFuncSetAttribute(k6_mma, cudaFuncAttributeMaxDynamicSharedMemorySize, K6_SMEM);

    k1_hmap<<<BATCH*TT*8, 512>>>(x);
    k2_mask<<<NB, 512>>>(Wmask);
    k3_mma<<<dim3(4, NBINS, 2), 256, K3_SMEM>>>(Wout);
    k3e_epi<<<992, 256>>>();
    k4_ff<<<dim3(4, NBINS), 256, K4_SMEM>>>(FF, gamma, beta, out1);
    k5c_rn<<<(NB + 255) / 256, 256>>>();
    k6_mma<<<dim3((NCLS + 63) / 64, NBINS), 256, K6_SMEM>>>(fc1d, out2);
}

// round 8
// speedup vs baseline: 1.9714x; 1.1001x over previous
#include <cuda_runtime.h>
#include <cuda_fp16.h>
#include <cstdint>

// ---------------- problem constants ----------------
#define BATCH 128
#define CH    256
#define TT    30
#define WW    11
#define HW    176
#define NBINS 31
#define RED   16
#define KDIM  4096
#define OUT   256
#define NCLS  10000
#define NB    (NBINS*BATCH)

#define LDA   136   // A smem row stride (fp16)
#define LDB   72    // B smem row stride (fp16)

// ---------------- scratch ----------------
__device__ float g_p[(size_t)NBINS*BATCH*TT*CH];
__device__ float g_pmax[NBINS*BATCH*CH];
__device__ __half g_pooled[(size_t)NBINS*BATCH*KDIM];      // fp16 single
__device__ __half g_feat_hi[NBINS*BATCH*CH];
__device__ __half g_feat_lo[NBINS*BATCH*CH];
__device__ __half g_bn[NBINS*BATCH*OUT];                   // fp16 single
__device__ float g_invrn[NB];
__device__ float g_rowsq[8][NB];
__device__ float g_part[(size_t)2*NBINS*BATCH*OUT];

// ---------------- helpers ----------------
__device__ __forceinline__ uint32_t smem_u32(const void* p) {
    uint32_t a;
    asm("{ .reg .u64 t; cvta.to.shared.u64 t, %1; cvt.u32.u64 %0, t; }" : "=r"(a) : "l"(p));
    return a;
}
__device__ __forceinline__ void cpa16(uint32_t dst, const void* src) {
    asm volatile("cp.async.cg.shared.global [%0], [%1], 16;" :: "r"(dst), "l"(src));
}
#define CPA_COMMIT() asm volatile("cp.async.commit_group;" ::: "memory")
#define CPA_WAIT0()  asm volatile("cp.async.wait_group 0;" ::: "memory")

__device__ __forceinline__ void ldsm4(uint32_t a[4], uint32_t addr) {
    asm volatile("ldmatrix.sync.aligned.m8n8.x4.shared.b16 {%0,%1,%2,%3}, [%4];"
        : "=r"(a[0]),"=r"(a[1]),"=r"(a[2]),"=r"(a[3]) : "r"(addr));
}
__device__ __forceinline__ void ldsm4t(uint32_t a[4], uint32_t addr) {
    asm volatile("ldmatrix.sync.aligned.m8n8.x4.trans.shared.b16 {%0,%1,%2,%3}, [%4];"
        : "=r"(a[0]),"=r"(a[1]),"=r"(a[2]),"=r"(a[3]) : "r"(addr));
}
__device__ __forceinline__ void mma_f16(float d[4], const uint32_t a[4], uint32_t b0, uint32_t b1) {
    asm volatile("mma.sync.aligned.m16n8k16.row.col.f32.f16.f16.f32 "
        "{%0,%1,%2,%3}, {%4,%5,%6,%7}, {%8,%9}, {%0,%1,%2,%3};"
        : "+f"(d[0]),"+f"(d[1]),"+f"(d[2]),"+f"(d[3])
        : "r"(a[0]),"r"(a[1]),"r"(a[2]),"r"(a[3]), "r"(b0),"r"(b1));
}
__device__ __forceinline__ unsigned pack2h(float a, float b) {
    __half2 h = __floats2half2_rn(a, b);
    return *reinterpret_cast<unsigned*>(&h);
}
__device__ __forceinline__ unsigned long long pack4h(float a, float b, float c, float d) {
    return ((unsigned long long)pack2h(c, d) << 32) | pack2h(a, b);
}
__device__ __forceinline__ float h_lo(float v) {
    return v - __half2float(__float2half_rn(v));
}

// single-pass fp16 tile step over one K=128 chunk: acc += A*B.
template<int MI, int NF>
__device__ __forceinline__ void mma_tile1(uint32_t sA, uint32_t sB,
                                          int lane, int warp_m, int warp_n,
                                          float (&acc)[MI][NF][4]) {
    const int l15 = lane & 15;
    const int l16 = (lane >> 4) << 3;
    #pragma unroll
    for (int ks = 0; ks < 8; ++ks) {
        const int k = ks * 16;
        uint32_t aa[MI][4], bb[NF][2];
        #pragma unroll
        for (int mi = 0; mi < MI; ++mi) {
            uint32_t ao = ((warp_m + mi*16 + l15)*LDA + k + l16) * 2;
            ldsm4(aa[mi], sA + ao);
        }
        #pragma unroll
        for (int q = 0; q < NF/2; ++q) {
            uint32_t bo = ((k + l15)*LDB + warp_n + q*16 + l16) * 2;
            uint32_t r[4];
            ldsm4t(r, sB + bo);
            bb[2*q][0] = r[0]; bb[2*q][1] = r[1];
            bb[2*q+1][0] = r[2]; bb[2*q+1][1] = r[3];
        }
        #pragma unroll
        for (int mi = 0; mi < MI; ++mi)
            #pragma unroll
            for (int nf = 0; nf < NF; ++nf)
                mma_f16(acc[mi][nf], aa[mi], bb[nf][0], bb[nf][1]);
    }
}

// two-pass (A hi/lo) tile step — used by k4 only.
template<int MI, int NF>
__device__ __forceinline__ void mma_tile2(uint32_t sAhi, uint32_t sAlo, uint32_t sB,
                                          int lane, int warp_m, int warp_n,
                                          float (&acc)[MI][NF][4]) {
    const int l15 = lane & 15;
    const int l16 = (lane >> 4) << 3;
    #pragma unroll
    for (int ks = 0; ks < 8; ++ks) {
        const int k = ks * 16;
        uint32_t ahi[MI][4], alo[MI][4], bb[NF][2];
        #pragma unroll
        for (int mi = 0; mi < MI; ++mi) {
            uint32_t ao = ((warp_m + mi*16 + l15)*LDA + k + l16) * 2;
            ldsm4(ahi[mi], sAhi + ao);
            ldsm4(alo[mi], sAlo + ao);
        }
        #pragma unroll
        for (int q = 0; q < NF/2; ++q) {
            uint32_t bo = ((k + l15)*LDB + warp_n + q*16 + l16) * 2;
            uint32_t r[4];
            ldsm4t(r, sB + bo);
            bb[2*q][0] = r[0]; bb[2*q][1] = r[1];
            bb[2*q+1][0] = r[2]; bb[2*q+1][1] = r[3];
        }
        #pragma unroll
        for (int mi = 0; mi < MI; ++mi)
            #pragma unroll
            for (int nf = 0; nf < NF; ++nf) {
                mma_f16(acc[mi][nf], ahi[mi], bb[nf][0], bb[nf][1]);
                mma_f16(acc[mi][nf], alo[mi], bb[nf][0], bb[nf][1]);
            }
    }
}

// =====================================================================
// K1: horizontal strip pooling.
// =====================================================================
__global__ __launch_bounds__(512) void k1_hmap(const float* __restrict__ x) {
    int bid = blockIdx.x;
    int cg = bid & 7;
    int t  = (bid >> 3) % TT;
    int b  = bid / (TT * 8);

    __shared__ float xs[32][180];
    __shared__ float rsum[32][16];
    __shared__ float rmax[32][16];

    const float* xb = x + (((size_t)b*CH + cg*32)*TT + t) * HW;
    int tid = threadIdx.x;

    for (int idx = tid; idx < 32*44; idx += 512) {
        int c = idx / 44, e = idx % 44;
        float4 v = *reinterpret_cast<const float4*>(xb + (size_t)c*TT*HW + e*4);
        *reinterpret_cast<float4*>(&xs[c][e*4]) = v;
    }
    __syncthreads();
    {
        int c = tid >> 4, h = tid & 15;
        float s = 0.f, m = -1e30f;
        #pragma unroll
        for (int w = 0; w < WW; ++w) {
            float v = xs[c][h*WW + w];
            s += v; m = fmaxf(m, v);
        }
        rsum[c][h] = s; rmax[c][h] = m;
    }
    __syncthreads();

    for (int oi = tid; oi < NBINS*32; oi += 512) {
        int n = oi >> 5;
        int c = oi & 31;
        int start, len;
        if      (n == 0) { start = 0;          len = 16; }
        else if (n < 3)  { start = (n-1)*8;    len = 8;  }
        else if (n < 7)  { start = (n-3)*4;    len = 4;  }
        else if (n < 15) { start = (n-7)*2;    len = 2;  }
        else             { start = n-15;       len = 1;  }
        float s = 0.f, m = -1e30f;
        for (int h = 0; h < len; ++h) {
            s += rsum[c][start+h];
            m = fmaxf(m, rmax[c][start+h]);
        }
        g_p[(((size_t)n*BATCH + b)*TT + t)*CH + cg*32 + c] = s / (float)(len*WW) + m;
    }
}

// =====================================================================
// K2: mask logits + softmax + attention pooling + pmax.
// Pooled stored as fp16 (single).
// =====================================================================
__global__ __launch_bounds__(512) void k2_mask(const float* __restrict__ Wmask) {
    int nb = blockIdx.x;
    int n = nb >> 7;
    int b = nb & 127;
    __shared__ float ps[TT][CH];
    __shared__ float wms[CH][RED];
    __shared__ float lg[TT][RED];

    int tid = threadIdx.x;
    const float* pg = g_p + ((size_t)n*BATCH + b)*TT*CH;
    for (int i = tid; i < TT*CH/4; i += 512) {
        float4 v = *reinterpret_cast<const float4*>(pg + i*4);
        *reinterpret_cast<float4*>(&ps[0][0] + i*4) = v;
    }
    const float* wg = Wmask + (size_t)n*CH*RED;
    for (int i = tid; i < CH*RED/4; i += 512) {
        float4 v = *reinterpret_cast<const float4*>(wg + i*4);
        *reinterpret_cast<float4*>(&wms[0][0] + i*4) = v;
    }
    __syncthreads();

    if (tid < TT*RED) {
        int t = tid >> 4, r = tid & 15;
        float acc = 0.f;
        #pragma unroll 8
        for (int c = 0; c < CH; ++c) acc += ps[t][c] * wms[c][r];
        lg[t][r] = acc;
    }
    __syncthreads();

    if (tid < RED) {
        int r = tid;
        float m = -1e30f;
        for (int t = 0; t < TT; ++t) m = fmaxf(m, lg[t][r]);
        float s = 0.f;
        for (int t = 0; t < TT; ++t) { float e = expf(lg[t][r] - m); lg[t][r] = e; s += e; }
        float inv = 1.f / s;
        for (int t = 0; t < TT; ++t) lg[t][r] *= inv;
    }
    __syncthreads();

    {
        int c = tid & 255;
        int rh = tid >> 8;
        float acc[8];
        #pragma unroll
        for (int r = 0; r < 8; ++r) acc[r] = 0.f;
        float pm = -1e30f;
        for (int t = 0; t < TT; ++t) {
            float pv = ps[t][c];
            pm = fmaxf(pm, pv);
            float4 m0 = *reinterpret_cast<const float4*>(&lg[t][rh*8]);
            float4 m1 = *reinterpret_cast<const float4*>(&lg[t][rh*8+4]);
            acc[0] += pv*m0.x; acc[1] += pv*m0.y; acc[2] += pv*m0.z; acc[3] += pv*m0.w;
            acc[4] += pv*m1.x; acc[5] += pv*m1.y; acc[6] += pv*m1.z; acc[7] += pv*m1.w;
        }
        size_t base = ((size_t)n*BATCH + b)*KDIM + c*RED + rh*8;
        unsigned long long* dh = reinterpret_cast<unsigned long long*>(g_pooled + base);
        dh[0] = pack4h(acc[0],acc[1],acc[2],acc[3]);
        dh[1] = pack4h(acc[4],acc[5],acc[6],acc[7]);
        if (rh == 0) g_pmax[((size_t)n*BATCH + b)*CH + c] = pm;
    }
}

// =====================================================================
// K3 (fp16 single-pass, split-K=2, pipelined): partial = pooled @ Wout
// BM=128, BN=64. grid (4 N, NBINS, 2 Ksplit) = 248 CTAs, occ 2.
// =====================================================================
#define ATILE (128*LDA*2)          // 34816
#define BTILE (128*LDB*2)          // 18432
#define K3_SMEM  (ATILE + BTILE)   // 53248

__global__ __launch_bounds__(256, 2) void k3_mma(const float* __restrict__ Wout) {
    extern __shared__ char smem[];
    const int n    = blockIdx.y;
    const int n0   = blockIdx.x * 64;
    const int ksp  = blockIdx.z;
    const int kbase = ksp * 2048;
    const int tid = threadIdx.x;
    const int lane = tid & 31, wid = tid >> 5;
    const int warp_m = (wid >> 1) * 32, warp_n = (wid & 1) * 32;
    const uint32_t sb = smem_u32(smem);
    const uint32_t sA = sb, sB = sb + ATILE;

    const __half* A = g_pooled + (size_t)n*BATCH*KDIM;
    const float* B = Wout + (size_t)n*KDIM*OUT;

    float acc[2][4][4];
    #pragma unroll
    for (int mi = 0; mi < 2; ++mi)
        #pragma unroll
        for (int nf = 0; nf < 4; ++nf)
            #pragma unroll
            for (int j = 0; j < 4; ++j) acc[mi][nf][j] = 0.f;

    const int cg = (tid & 15) * 4;
    const int kr = tid >> 4;
    const int arow = tid >> 4, ac8 = (tid & 15) * 8;

    float4 rB[8];
    #pragma unroll
    for (int i = 0; i < 8; ++i)
        rB[i] = *reinterpret_cast<const float4*>(B + (size_t)(kbase + kr + i*16)*OUT + n0 + cg);

    for (int kc = 0; kc < 16; ++kc) {
        #pragma unroll
        for (int i = 0; i < 8; ++i) {
            int row = arow + i*16;
            cpa16(sA + (uint32_t)(row*LDA + ac8) * 2,
                  A + (size_t)row*KDIM + kbase + kc*128 + ac8);
        }
        CPA_COMMIT();
        #pragma unroll
        for (int i = 0; i < 8; ++i) {
            float4 v = rB[i];
            int o = ((kr + i*16)*LDB + cg) * 2;
            *reinterpret_cast<unsigned long long*>(smem + ATILE + o) =
                pack4h(v.x, v.y, v.z, v.w);
        }
        CPA_WAIT0();
        __syncthreads();
        if (kc + 1 < 16) {
            #pragma unroll
            for (int i = 0; i < 8; ++i)
                rB[i] = *reinterpret_cast<const float4*>(
                    B + (size_t)(kbase + (kc+1)*128 + kr + i*16)*OUT + n0 + cg);
        }
        mma_tile1<2,4>(sA, sB, lane, warp_m, warp_n, acc);
        __syncthreads();
    }

    float* pp = g_part + ((size_t)ksp*NBINS + n)*BATCH*OUT;
    const int g = lane >> 2, t2 = (lane & 3) * 2;
    #pragma unroll
    for (int mi = 0; mi < 2; ++mi) {
        #pragma unroll
        for (int nf = 0; nf < 4; ++nf) {
            int col = n0 + warp_n + nf*8 + t2;
            #pragma unroll
            for (int h = 0; h < 2; ++h) {
                int row = warp_m + mi*16 + g + h*8;
                *reinterpret_cast<float2*>(pp + (size_t)row*OUT + col) =
                    make_float2(acc[mi][nf][2*h], acc[mi][nf][2*h+1]);
            }
        }
    }
}

// K3 epilogue: feat = pmax + leaky(part0+part1) -> fp16 hi/lo.
__global__ __launch_bounds__(256) void k3e_epi() {
    int i4 = blockIdx.x * 256 + threadIdx.x;   // < 253952
    const float4* p0 = reinterpret_cast<const float4*>(g_part);
    const float4* p1 = reinterpret_cast<const float4*>(g_part + (size_t)NBINS*BATCH*OUT);
    const float4* pm = reinterpret_cast<const float4*>(g_pmax);
    float4 a = p0[i4], b = p1[i4], m = pm[i4];
    float o[4];
    float s;
    s = a.x + b.x; o[0] = ((s >= 0.f) ? s : 0.01f*s) + m.x;
    s = a.y + b.y; o[1] = ((s >= 0.f) ? s : 0.01f*s) + m.y;
    s = a.z + b.z; o[2] = ((s >= 0.f) ? s : 0.01f*s) + m.z;
    s = a.w + b.w; o[3] = ((s >= 0.f) ? s : 0.01f*s) + m.w;
    reinterpret_cast<unsigned long long*>(g_feat_hi)[i4] = pack4h(o[0], o[1], o[2], o[3]);
    reinterpret_cast<unsigned long long*>(g_feat_lo)[i4] =
        pack4h(h_lo(o[0]), h_lo(o[1]), h_lo(o[2]), h_lo(o[3]));
}

// =====================================================================
// K4 (fp16x2 + fused BatchNorm): outputs = feat @ FForward.
// BM=128 (full batch), BN=64, K=256. grid (4, NBINS), occ 2.
// =====================================================================
#define K4_SMEM  (2*ATILE + BTILE)     // 88064; obuf reuse = 33.8KB

__global__ __launch_bounds__(256, 2) void k4_ff(const float* __restrict__ FF,
                                                const float* __restrict__ gamma,
                                                const float* __restrict__ beta,
                                                float* __restrict__ out1) {
    extern __shared__ char smem[];
    const int n  = blockIdx.y;
    const int n0 = blockIdx.x * 64;
    const int tid = threadIdx.x;
    const int lane = tid & 31, wid = tid >> 5;
    const int warp_m = (wid >> 1) * 32, warp_n = (wid & 1) * 32;
    const uint32_t sb = smem_u32(smem);
    const uint32_t sAhi = sb, sAlo = sb + ATILE, sB = sb + 2*ATILE;

    const __half* Ah = g_feat_hi + (size_t)n*BATCH*CH;
    const __half* Al = g_feat_lo + (size_t)n*BATCH*CH;
    const float* B = FF + (size_t)n*CH*OUT;

    float acc[2][4][4];
    #pragma unroll
    for (int mi = 0; mi < 2; ++mi)
        #pragma unroll
        for (int nf = 0; nf < 4; ++nf)
            #pragma unroll
            for (int j = 0; j < 4; ++j) acc[mi][nf][j] = 0.f;

    const int cg = (tid & 15) * 4;
    const int kr = tid >> 4;
    const int arow = tid >> 4, ac8 = (tid & 15) * 8;

    float4 rB[8];
    #pragma unroll
    for (int i = 0; i < 8; ++i)
        rB[i] = *reinterpret_cast<const float4*>(B + (size_t)(kr + i*16)*OUT + n0 + cg);

    for (int kc = 0; kc < 2; ++kc) {
        #pragma unroll
        for (int i = 0; i < 8; ++i) {
            int row = arow + i*16;
            size_t gA = (size_t)row*CH + kc*128 + ac8;
            uint32_t so = (uint32_t)(row*LDA + ac8) * 2;
            cpa16(sAhi + so, Ah + gA);
            cpa16(sAlo + so, Al + gA);
        }
        CPA_COMMIT();
        #pragma unroll
        for (int i = 0; i < 8; ++i) {
            float4 v = rB[i];
            int o = ((kr + i*16)*LDB + cg) * 2;
            *reinterpret_cast<unsigned long long*>(smem + 2*ATILE + o) =
                pack4h(v.x, v.y, v.z, v.w);
        }
        CPA_WAIT0();
        __syncthreads();
        if (kc == 0) {
            #pragma unroll
            for (int i = 0; i < 8; ++i)
                rB[i] = *reinterpret_cast<const float4*>(
                    B + (size_t)(128 + kr + i*16)*OUT + n0 + cg);
        }
        mma_tile2<2,4>(sAhi, sAlo, sB, lane, warp_m, warp_n, acc);
        __syncthreads();
    }

    // ---- fused BatchNorm epilogue ----
    float* ob = reinterpret_cast<float*>(smem);        // [128][65]
    float* smean = ob + 128*65;
    float* sistd = smean + 64;
    const int g = lane >> 2, t2 = (lane & 3) * 2;

    #pragma unroll
    for (int mi = 0; mi < 2; ++mi)
        #pragma unroll
        for (int nf = 0; nf < 4; ++nf) {
            int col = warp_n + nf*8 + t2;
            #pragma unroll
            for (int h = 0; h < 2; ++h) {
                int row = warp_m + mi*16 + g + h*8;
                ob[row*65 + col]     = acc[mi][nf][2*h];
                ob[row*65 + col + 1] = acc[mi][nf][2*h+1];
            }
        }
    __syncthreads();

    if (tid < 64) {
        float s = 0.f;
        #pragma unroll 8
        for (int r = 0; r < 128; ++r) s += ob[r*65 + tid];
        float mean = s * (1.f/128.f);
        float v = 0.f;
        #pragma unroll 8
        for (int r = 0; r < 128; ++r) { float d = ob[r*65 + tid] - mean; v += d*d; }
        smean[tid] = mean;
        sistd[tid] = rsqrtf(v * (1.f/128.f) + 1e-5f);
    }
    __syncthreads();

    const int slot = blockIdx.x * 2 + (wid & 1);
    #pragma unroll
    for (int mi = 0; mi < 2; ++mi) {
        #pragma unroll
        for (int h = 0; h < 2; ++h) {
            int row = warp_m + mi*16 + g + h*8;
            float rsq = 0.f;
            #pragma unroll
            for (int nf = 0; nf < 4; ++nf) {
                int col = warp_n + nf*8 + t2;
                float o0 = acc[mi][nf][2*h], o1 = acc[mi][nf][2*h+1];
                *reinterpret_cast<float2*>(
                    out1 + (size_t)row*(NBINS*OUT) + n*OUT + n0 + col) = make_float2(o0, o1);
                float b0 = gamma[n*OUT + n0 + col]   * (o0 - smean[col])   * sistd[col]   + beta[n*OUT + n0 + col];
                float b1 = gamma[n*OUT + n0 + col+1] * (o1 - smean[col+1]) * sistd[col+1] + beta[n*OUT + n0 + col+1];
                size_t bo = (size_t)n*BATCH*OUT + (size_t)row*OUT + n0 + col;
                *reinterpret_cast<unsigned*>(g_bn + bo) = pack2h(b0, b1);
                rsq += b0*b0 + b1*b1;
            }
            rsq += __shfl_xor_sync(0xffffffffu, rsq, 1);
            rsq += __shfl_xor_sync(0xffffffffu, rsq, 2);
            if ((lane & 3) == 0) g_rowsq[slot][n*BATCH + row] = rsq;
        }
    }
}

// K5c: inverse row norms from 8 partials.
__global__ __launch_bounds__(256) void k5c_rn() {
    int idx = blockIdx.x * 256 + threadIdx.x;
    if (idx < NB) {
        float s = 0.f;
        #pragma unroll
        for (int j = 0; j < 8; ++j) s += g_rowsq[j][idx];
        g_invrn[idx] = 1.f / fmaxf(sqrtf(s), 1e-12f);
    }
}

// =====================================================================
// K6 (fp16 single-pass, pipelined): logits = (bn @ fc1d) * invrow * invcol
// 128x64 tiles, grid (157, 31), occ 2. cp.async A + reg-prefetch B.
// =====================================================================
#define K6_CSQ   (ATILE + BTILE)             // 53248
#define K6_INV   (K6_CSQ + 16*64*4)          // 57344
#define K6_SMEM  (K6_INV + 64*4)             // 57600

__global__ __launch_bounds__(256, 2) void k6_mma(const float* __restrict__ fc,
                                                 float* __restrict__ out2) {
    extern __shared__ char smem[];
    const int n  = blockIdx.y;
    const int n0 = blockIdx.x * 64;
    const int tid = threadIdx.x;
    const int lane = tid & 31, wid = tid >> 5;
    const int warp_m = (wid >> 1) * 32, warp_n = (wid & 1) * 32;
    const uint32_t sb = smem_u32(smem);
    const uint32_t sA = sb, sB = sb + ATILE;

    const __half* A = g_bn + (size_t)n*BATCH*OUT;
    const float* Bg = fc + (size_t)n*OUT*NCLS;

    float acc[2][4][4];
    #pragma unroll
    for (int mi = 0; mi < 2; ++mi)
        #pragma unroll
        for (int nf = 0; nf < 4; ++nf)
            #pragma unroll
            for (int j = 0; j < 4; ++j) acc[mi][nf][j] = 0.f;

    const int cg = (tid & 15) * 4;
    const int kr = tid >> 4;
    const int arow = tid >> 4, ac8 = (tid & 15) * 8;
    const bool valid = (n0 + cg) < NCLS;
    float sq0 = 0.f, sq1 = 0.f, sq2 = 0.f, sq3 = 0.f;

    float4 rB[8];
    #pragma unroll
    for (int i = 0; i < 8; ++i)
        rB[i] = valid ? *reinterpret_cast<const float4*>(
                            Bg + (size_t)(kr + i*16)*NCLS + n0 + cg)
                      : make_float4(0.f, 0.f, 0.f, 0.f);

    for (int kc = 0; kc < 2; ++kc) {
        #pragma unroll
        for (int i = 0; i < 8; ++i) {
            int row = arow + i*16;
            cpa16(sA + (uint32_t)(row*LDA + ac8) * 2,
                  A + (size_t)row*OUT + kc*128 + ac8);
        }
        CPA_COMMIT();
        #pragma unroll
        for (int i = 0; i < 8; ++i) {
            float4 v = rB[i];
            sq0 += v.x*v.x; sq1 += v.y*v.y; sq2 += v.z*v.z; sq3 += v.w*v.w;
            int o = ((kr + i*16)*LDB + cg) * 2;
            *reinterpret_cast<unsigned long long*>(smem + ATILE + o) =
                pack4h(v.x, v.y, v.z, v.w);
        }
        CPA_WAIT0();
        __syncthreads();
        if (kc == 0) {
            #pragma unroll
            for (int i = 0; i < 8; ++i)
                rB[i] = valid ? *reinterpret_cast<const float4*>(
                                    Bg + (size_t)(128 + kr + i*16)*NCLS + n0 + cg)
                              : make_float4(0.f, 0.f, 0.f, 0.f);
        }
        mma_tile1<2,4>(sA, sB, lane, warp_m, warp_n, acc);
        __syncthreads();
    }

    // column inv-norms
    float* csq = reinterpret_cast<float*>(smem + K6_CSQ);
    *reinterpret_cast<float4*>(csq + kr*64 + cg) = make_float4(sq0, sq1, sq2, sq3);
    __syncthreads();
    float* inv = reinterpret_cast<float*>(smem + K6_INV);
    if (tid < 64) {
        float ss = 0.f;
        #pragma unroll
        for (int r = 0; r < 16; ++r) ss += csq[r*64 + tid];
        inv[tid] = 1.f / fmaxf(sqrtf(ss), 1e-12f);
    }
    __syncthreads();

    const int g = lane >> 2, t2 = (lane & 3) * 2;
    #pragma unroll
    for (int mi = 0; mi < 2; ++mi) {
        #pragma unroll
        for (int nf = 0; nf < 4; ++nf) {
            int col = warp_n + nf*8 + t2;
            if (n0 + col >= NCLS) continue;
            float ic0 = inv[col], ic1 = inv[col+1];
            #pragma unroll
            for (int h = 0; h < 2; ++h) {
                int row = warp_m + mi*16 + g + h*8;
                float ir = g_invrn[n*BATCH + row];
                *reinterpret_cast<float2*>(
                    out2 + (size_t)row*(NBINS*NCLS) + n*NCLS + n0 + col) =
                    make_float2(acc[mi][nf][2*h]*ir*ic0, acc[mi][nf][2*h+1]*ir*ic1);
            }
        }
    }
}

// =====================================================================
extern "C" void kernel_launch(void* const* d_in, const int* in_sizes, int n_in,
                              void* d_out, int out_size) {
    const float* x     = (const float*)d_in[0];
    const float* Wmask = (const float*)d_in[1];
    const float* Wout  = (const float*)d_in[2];
    const float* FF    = (const float*)d_in[3];
    const float* gamma = (const float*)d_in[4];
    const float* beta  = (const float*)d_in[5];
    const float* fc1d  = (const float*)d_in[6];
    float* out  = (float*)d_out;
    float* out1 = out;                                   // [128,31,256]
    float* out2 = out + (size_t)BATCH*NBINS*OUT;         // [128,31,10000]

    cudaFuncSetAttribute(k3_mma, cudaFuncAttributeMaxDynamicSharedMemorySize, K3_SMEM);
    cudaFuncSetAttribute(k4_ff,  cudaFuncAttributeMaxDynamicSharedMemorySize, K4_SMEM);
    cudaFuncSetAttribute(k6_mma, cudaFuncAttributeMaxDynamicSharedMemorySize, K6_SMEM);

    k1_hmap<<<BATCH*TT*8, 512>>>(x);
    k2_mask<<<NB, 512>>>(Wmask);
    k3_mma<<<dim3(4, NBINS, 2), 256, K3_SMEM>>>(Wout);
    k3e_epi<<<992, 256>>>();
    k4_ff<<<dim3(4, NBINS), 256, K4_SMEM>>>(FF, gamma, beta, out1);
    k5c_rn<<<(NB + 255) / 256, 256>>>();
    k6_mma<<<dim3((NCLS + 63) / 64, NBINS), 256, K6_SMEM>>>(fc1d, out2);
}